// round 1
// baseline (speedup 1.0000x reference)
#include <cuda_runtime.h>

#define NN  50000
#define NE  800000
#define FIN 256
#define H1  4
#define D1  64
#define C2  47

// ---------------- scratch (device globals; no allocation allowed) ----------------
__device__ __align__(16) float g_fs1[(size_t)NN * FIN];   // layer-1 projected features [N,4,64]
__device__ __align__(16) float g_h2 [(size_t)NN * FIN];   // relu(layer-1 output) [N,256]
__device__ __align__(16) float g_el1[NN * H1];
__device__ __align__(16) float g_er1[NN * H1];
__device__ __align__(16) float g_fs2[(size_t)NN * C2];    // layer-2 projected features [N,47]
__device__ __align__(16) float g_el2[NN];
__device__ __align__(16) float g_er2[NN];
__device__ __align__(16) int   g_rowptr[NN + 1];

// ---------------- SGEMM core: C[M,N] = A[M,K] * B[K,N] (row-major) ----------------
// BM=128, BN=64, BK=16, 256 threads, 8x4 per thread.
template <int N, int K>
__device__ __forceinline__ void sgemm_core(const float* __restrict__ A,
                                           const float* __restrict__ B,
                                           float* __restrict__ C, int M)
{
    __shared__ float As[16][128];
    __shared__ float Bs[16][64];
    const int tid = threadIdx.x;           // 0..255
    const int tx  = tid & 15;              // 16 col-threads
    const int ty  = tid >> 4;              // 16 row-threads
    const int row0 = blockIdx.y * 128;
    const int col0 = blockIdx.x * 64;

    float acc[8][4];
#pragma unroll
    for (int i = 0; i < 8; ++i)
#pragma unroll
        for (int j = 0; j < 4; ++j) acc[i][j] = 0.f;

    for (int k0 = 0; k0 < K; k0 += 16) {
        // load A tile: 128x16 = 2048 elems, 8 per thread
#pragma unroll
        for (int i = 0; i < 8; ++i) {
            int e = tid + i * 256;
            int r = e >> 4, kk = e & 15;
            int gr = row0 + r;
            As[kk][r] = (gr < M) ? A[(size_t)gr * K + k0 + kk] : 0.f;
        }
        // load B tile: 16x64 = 1024 elems, 4 per thread
#pragma unroll
        for (int i = 0; i < 4; ++i) {
            int e = tid + i * 256;
            int kk = e >> 6, c = e & 63;
            int gc = col0 + c;
            Bs[kk][c] = (gc < N) ? B[(size_t)(k0 + kk) * N + gc] : 0.f;
        }
        __syncthreads();
#pragma unroll
        for (int kk = 0; kk < 16; ++kk) {
            float ra[8], rb[4];
#pragma unroll
            for (int i = 0; i < 8; ++i) ra[i] = As[kk][ty * 8 + i];
#pragma unroll
            for (int j = 0; j < 4; ++j) rb[j] = Bs[kk][tx * 4 + j];
#pragma unroll
            for (int i = 0; i < 8; ++i)
#pragma unroll
                for (int j = 0; j < 4; ++j)
                    acc[i][j] = fmaf(ra[i], rb[j], acc[i][j]);
        }
        __syncthreads();
    }
#pragma unroll
    for (int i = 0; i < 8; ++i) {
        int gr = row0 + ty * 8 + i;
        if (gr < M) {
#pragma unroll
            for (int j = 0; j < 4; ++j) {
                int gc = col0 + tx * 4 + j;
                if (gc < N) C[(size_t)gr * N + gc] = acc[i][j];
            }
        }
    }
}

__global__ void sgemm1_kernel(const float* __restrict__ A, const float* __restrict__ B)
{
    sgemm_core<256, 256>(A, B, g_fs1, NN);
}
__global__ void sgemm2_kernel(const float* __restrict__ B)
{
    sgemm_core<C2, 256>(g_h2, B, g_fs2, NN);
}

// ---------------- per-node attention logits, layer 1 (warp per node) ----------------
__global__ void att1_kernel(const float* __restrict__ al, const float* __restrict__ ar)
{
    int warp = (blockIdx.x * blockDim.x + threadIdx.x) >> 5;
    int lane = threadIdx.x & 31;
    if (warp >= NN) return;
    const float* row = g_fs1 + (size_t)warp * 256;
#pragma unroll
    for (int h = 0; h < 4; ++h) {
        float v1 = row[h * 64 + lane];
        float v2 = row[h * 64 + 32 + lane];
        float a = v1 * al[h * 64 + lane] + v2 * al[h * 64 + 32 + lane];
        float b = v1 * ar[h * 64 + lane] + v2 * ar[h * 64 + 32 + lane];
#pragma unroll
        for (int off = 16; off; off >>= 1) {
            a += __shfl_xor_sync(0xffffffffu, a, off);
            b += __shfl_xor_sync(0xffffffffu, b, off);
        }
        if (lane == 0) { g_el1[warp * 4 + h] = a; g_er1[warp * 4 + h] = b; }
    }
}

// ---------------- per-node attention logits, layer 2 (warp per node) ----------------
__global__ void att2_kernel(const float* __restrict__ al2, const float* __restrict__ ar2)
{
    int warp = (blockIdx.x * blockDim.x + threadIdx.x) >> 5;
    int lane = threadIdx.x & 31;
    if (warp >= NN) return;
    const float* row = g_fs2 + (size_t)warp * C2;
    float a = 0.f, b = 0.f;
    if (lane < C2)      { float v = row[lane];      a  = v * al2[lane];      b  = v * ar2[lane]; }
    if (lane + 32 < C2) { float v = row[lane + 32]; a += v * al2[lane + 32]; b += v * ar2[lane + 32]; }
#pragma unroll
    for (int off = 16; off; off >>= 1) {
        a += __shfl_xor_sync(0xffffffffu, a, off);
        b += __shfl_xor_sync(0xffffffffu, b, off);
    }
    if (lane == 0) { g_el2[warp] = a; g_er2[warp] = b; }
}

// ---------------- CSR row pointers from sorted dst (binary search) ----------------
__global__ void rowptr_kernel(const int* __restrict__ dst)
{
    int n = blockIdx.x * blockDim.x + threadIdx.x;
    if (n > NN) return;
    int lo = 0, hi = NE;
    while (lo < hi) {
        int mid = (lo + hi) >> 1;
        if (dst[mid] < n) lo = mid + 1; else hi = mid;
    }
    g_rowptr[n] = lo;
}

// ---------------- layer-1 segment softmax + aggregation (block per dst node) ----------------
// 256 threads: t -> (h = t>>6, d = t&63). Output: g_h2 = relu(agg + b1).
__global__ void agg1_kernel(const int* __restrict__ src, const float* __restrict__ b1)
{
    const int n = blockIdx.x;
    const int t = threadIdx.x;
    const int h = t >> 6;
    const int s = g_rowptr[n];
    const int e = g_rowptr[n + 1];

    __shared__ float er_sh[4];
    __shared__ float sm_mx[4];
    __shared__ float s_wred[8 * 4];
    __shared__ float sm_w[256];
    __shared__ int   sm_src[64];

    if (t < 4) er_sh[t] = g_er1[n * 4 + t];
    __syncthreads();

    // pass 1: per-head max of leaky(el[src]+er[n]) over edges
    float mx0 = -1e30f, mx1 = -1e30f, mx2 = -1e30f, mx3 = -1e30f;
    for (int j = s + t; j < e; j += 256) {
        int sj = src[j];
        float4 ev = *reinterpret_cast<const float4*>(g_el1 + sj * 4);
        float v;
        v = ev.x + er_sh[0]; v = v > 0.f ? v : 0.2f * v; mx0 = fmaxf(mx0, v);
        v = ev.y + er_sh[1]; v = v > 0.f ? v : 0.2f * v; mx1 = fmaxf(mx1, v);
        v = ev.z + er_sh[2]; v = v > 0.f ? v : 0.2f * v; mx2 = fmaxf(mx2, v);
        v = ev.w + er_sh[3]; v = v > 0.f ? v : 0.2f * v; mx3 = fmaxf(mx3, v);
    }
#pragma unroll
    for (int off = 16; off; off >>= 1) {
        mx0 = fmaxf(mx0, __shfl_xor_sync(0xffffffffu, mx0, off));
        mx1 = fmaxf(mx1, __shfl_xor_sync(0xffffffffu, mx1, off));
        mx2 = fmaxf(mx2, __shfl_xor_sync(0xffffffffu, mx2, off));
        mx3 = fmaxf(mx3, __shfl_xor_sync(0xffffffffu, mx3, off));
    }
    int lane = t & 31, wid = t >> 5;
    if (lane == 0) {
        s_wred[wid * 4 + 0] = mx0; s_wred[wid * 4 + 1] = mx1;
        s_wred[wid * 4 + 2] = mx2; s_wred[wid * 4 + 3] = mx3;
    }
    __syncthreads();
    if (t < 4) {
        float m = -1e30f;
#pragma unroll
        for (int w = 0; w < 8; ++w) m = fmaxf(m, s_wred[w * 4 + t]);
        sm_mx[t] = m;
    }
    __syncthreads();

    // pass 2: chunked. Phase A computes exp weights once per (edge,head) into
    // shared; Phase B: every thread accumulates its (h,d) over all edges, so
    // the per-head denominator falls out for free (no reduction needed).
    float acc = 0.f, den = 0.f;
    for (int base = s; base < e; base += 64) {
        int cnt = min(64, e - base);
        if (t < cnt * 4) {
            int jj = t >> 2, hh = t & 3;
            int sj = src[base + jj];
            if (hh == 0) sm_src[jj] = sj;
            float v = g_el1[sj * 4 + hh] + er_sh[hh];
            v = v > 0.f ? v : 0.2f * v;
            sm_w[t] = __expf(v - sm_mx[hh]);
        }
        __syncthreads();
#pragma unroll 4
        for (int jj = 0; jj < cnt; ++jj) {
            float w = sm_w[jj * 4 + h];
            int sj = sm_src[jj];
            den += w;
            acc = fmaf(w, g_fs1[(size_t)sj * 256 + t], acc);
        }
        __syncthreads();
    }

    float bb = b1[t];
    float o = (e > s) ? (acc / den + bb) : bb;
    g_h2[(size_t)n * 256 + t] = fmaxf(o, 0.f);
}

// ---------------- layer-2 segment softmax + aggregation (block per dst node, H=1, D=47) ----------------
__global__ void agg2_kernel(const int* __restrict__ src, const float* __restrict__ b2,
                            float* __restrict__ out)
{
    const int n = blockIdx.x;
    const int t = threadIdx.x;   // 64 threads
    const int s = g_rowptr[n];
    const int e = g_rowptr[n + 1];

    __shared__ float sm_w[64];
    __shared__ int   sm_src[64];
    __shared__ float s_wred[2];
    __shared__ float sm_mxv;

    float ern = g_er2[n];

    float mx = -1e30f;
    for (int j = s + t; j < e; j += 64) {
        float v = g_el2[src[j]] + ern;
        v = v > 0.f ? v : 0.2f * v;
        mx = fmaxf(mx, v);
    }
#pragma unroll
    for (int off = 16; off; off >>= 1)
        mx = fmaxf(mx, __shfl_xor_sync(0xffffffffu, mx, off));
    if ((t & 31) == 0) s_wred[t >> 5] = mx;
    __syncthreads();
    if (t == 0) sm_mxv = fmaxf(s_wred[0], s_wred[1]);
    __syncthreads();
    float mxv = sm_mxv;

    float acc = 0.f, den = 0.f;
    for (int base = s; base < e; base += 64) {
        int cnt = min(64, e - base);
        if (t < cnt) {
            int sj = src[base + t];
            sm_src[t] = sj;
            float v = g_el2[sj] + ern;
            v = v > 0.f ? v : 0.2f * v;
            sm_w[t] = __expf(v - mxv);
        }
        __syncthreads();
#pragma unroll 4
        for (int jj = 0; jj < cnt; ++jj) {
            float w = sm_w[jj];
            den += w;
            if (t < C2)
                acc = fmaf(w, g_fs2[(size_t)sm_src[jj] * C2 + t], acc);
        }
        __syncthreads();
    }

    if (t < C2) {
        float bb = b2[t];
        out[(size_t)n * C2 + t] = (e > s) ? (acc / den + bb) : bb;
    }
}

// ---------------- launch ----------------
extern "C" void kernel_launch(void* const* d_in, const int* in_sizes, int n_in,
                              void* d_out, int out_size)
{
    const float* x   = (const float*)d_in[0];
    const float* W1  = (const float*)d_in[1];
    const float* al1 = (const float*)d_in[2];
    const float* ar1 = (const float*)d_in[3];
    const float* b1  = (const float*)d_in[4];
    const float* W2  = (const float*)d_in[5];
    const float* al2 = (const float*)d_in[6];
    const float* ar2 = (const float*)d_in[7];
    const float* b2  = (const float*)d_in[8];
    const int*   src = (const int*)d_in[9];
    const int*   dst = (const int*)d_in[10];
    float* out = (float*)d_out;

    (void)in_sizes; (void)n_in; (void)out_size;

    // CSR row pointers from sorted dst
    rowptr_kernel<<<(NN + 1 + 255) / 256, 256>>>(dst);

    // Layer 1
    {
        dim3 grid((256 + 63) / 64, (NN + 127) / 128);
        sgemm1_kernel<<<grid, 256>>>(x, W1);
    }
    att1_kernel<<<(NN + 7) / 8, 256>>>(al1, ar1);
    agg1_kernel<<<NN, 256>>>(src, b1);

    // Layer 2
    {
        dim3 grid((C2 + 63) / 64, (NN + 127) / 128);
        sgemm2_kernel<<<grid, 256>>>(W2);
    }
    att2_kernel<<<(NN + 7) / 8, 256>>>(al2, ar2);
    agg2_kernel<<<NN, 64>>>(src, b2, out);
}

// round 2
// speedup vs baseline: 1.4046x; 1.4046x over previous
#include <cuda_runtime.h>

#define NN  50000
#define NE  800000
#define FIN 256
#define H1  4
#define D1  64
#define C2  47

// ---------------- scratch (device globals; no allocation allowed) ----------------
__device__ __align__(16) float g_fs1[(size_t)NN * FIN];   // layer-1 projected features [N,4,64]
__device__ __align__(16) float g_h2 [(size_t)NN * FIN];   // relu(layer-1 output) [N,256]
__device__ __align__(16) float g_el1[NN * H1];
__device__ __align__(16) float g_er1[NN * H1];
__device__ __align__(16) float g_fs2[(size_t)NN * C2];    // layer-2 projected features [N,47]
__device__ __align__(16) float g_el2[NN];
__device__ __align__(16) float g_er2[NN];
__device__ __align__(16) int   g_rowptr[NN + 1];

// ---------------- packed fp32x2 FMA (Blackwell f32x2 pipe, 2 MACs / issue) ----------------
__device__ __forceinline__ void fma_x2(float2& d, const float2& a, const float2& b)
{
    asm("fma.rn.f32x2 %0, %1, %2, %0;"
        : "+l"(reinterpret_cast<unsigned long long&>(d))
        : "l"(reinterpret_cast<const unsigned long long&>(a)),
          "l"(reinterpret_cast<const unsigned long long&>(b)));
}

// ---------------- SGEMM: C[M,N] = A[M,K]*B[K,N], BM=128 BN=64 BK=16, 256 thr, 8x4/thr ----
// A tile stored as duplicated (a,a) float2 pairs so the f32x2 FMA needs no packing MOVs.
template <int N, int K, bool VEC>
__global__ void sgemm_kernel(const float* __restrict__ A, const float* __restrict__ B,
                             float* __restrict__ C, int M)
{
    __shared__ float2 As2[16][130];   // padded stride: avoids STS bank conflicts, keeps 16B align
    __shared__ float  Bs[16][64];

    const int tid = threadIdx.x;
    const int tx  = tid & 15;
    const int ty  = tid >> 4;
    const int row0 = blockIdx.y * 128;
    const int col0 = blockIdx.x * 64;

    float2 acc[8][2];
#pragma unroll
    for (int i = 0; i < 8; ++i) { acc[i][0] = make_float2(0.f, 0.f); acc[i][1] = make_float2(0.f, 0.f); }

    for (int k0 = 0; k0 < K; k0 += 16) {
        // A tile: 128 rows x 16 k. 512 float4 loads -> duplicated float2 stores.
#pragma unroll
        for (int i = 0; i < 2; ++i) {
            int idx = tid + i * 256;          // 0..511
            int r = idx >> 2, q = idx & 3;    // row, float4-within-row
            int gr = row0 + r;
            float4 v = make_float4(0.f, 0.f, 0.f, 0.f);
            if (gr < M) v = *reinterpret_cast<const float4*>(A + (size_t)gr * K + k0 + q * 4);
            As2[q * 4 + 0][r] = make_float2(v.x, v.x);
            As2[q * 4 + 1][r] = make_float2(v.y, v.y);
            As2[q * 4 + 2][r] = make_float2(v.z, v.z);
            As2[q * 4 + 3][r] = make_float2(v.w, v.w);
        }
        // B tile: 16 x 64
        if (VEC) {
            int kk = tid >> 4, c = (tid & 15) * 4;
            float4 v = *reinterpret_cast<const float4*>(B + (size_t)(k0 + kk) * N + col0 + c);
            *reinterpret_cast<float4*>(&Bs[kk][c]) = v;
        } else {
#pragma unroll
            for (int i = 0; i < 4; ++i) {
                int e = tid + i * 256;
                int kk = e >> 6, c = e & 63;
                int gc = col0 + c;
                Bs[kk][c] = (gc < N) ? B[(size_t)(k0 + kk) * N + gc] : 0.f;
            }
        }
        __syncthreads();
#pragma unroll
        for (int kk = 0; kk < 16; ++kk) {
            float2 ra[8];
            const float4* pa = reinterpret_cast<const float4*>(&As2[kk][ty * 8]);
#pragma unroll
            for (int q = 0; q < 4; ++q) {
                float4 t = pa[q];
                ra[q * 2 + 0] = make_float2(t.x, t.y);
                ra[q * 2 + 1] = make_float2(t.z, t.w);
            }
            float4 bq = *reinterpret_cast<const float4*>(&Bs[kk][tx * 4]);
            float2 rb0 = make_float2(bq.x, bq.y);
            float2 rb1 = make_float2(bq.z, bq.w);
#pragma unroll
            for (int i = 0; i < 8; ++i) {
                fma_x2(acc[i][0], ra[i], rb0);
                fma_x2(acc[i][1], ra[i], rb1);
            }
        }
        __syncthreads();
    }
#pragma unroll
    for (int i = 0; i < 8; ++i) {
        int gr = row0 + ty * 8 + i;
        if (gr >= M) continue;
        if (VEC) {
            *reinterpret_cast<float2*>(C + (size_t)gr * N + col0 + tx * 4)     = acc[i][0];
            *reinterpret_cast<float2*>(C + (size_t)gr * N + col0 + tx * 4 + 2) = acc[i][1];
        } else {
            int gc = col0 + tx * 4;
            if (gc + 0 < N) C[(size_t)gr * N + gc + 0] = acc[i][0].x;
            if (gc + 1 < N) C[(size_t)gr * N + gc + 1] = acc[i][0].y;
            if (gc + 2 < N) C[(size_t)gr * N + gc + 2] = acc[i][1].x;
            if (gc + 3 < N) C[(size_t)gr * N + gc + 3] = acc[i][1].y;
        }
    }
}

// ---------------- per-node attention logits, layer 1 (warp per node) ----------------
__global__ void att1_kernel(const float* __restrict__ al, const float* __restrict__ ar)
{
    int warp = (blockIdx.x * blockDim.x + threadIdx.x) >> 5;
    int lane = threadIdx.x & 31;
    if (warp >= NN) return;
    const float* row = g_fs1 + (size_t)warp * 256;
#pragma unroll
    for (int h = 0; h < 4; ++h) {
        float v1 = row[h * 64 + lane];
        float v2 = row[h * 64 + 32 + lane];
        float a = v1 * al[h * 64 + lane] + v2 * al[h * 64 + 32 + lane];
        float b = v1 * ar[h * 64 + lane] + v2 * ar[h * 64 + 32 + lane];
#pragma unroll
        for (int off = 16; off; off >>= 1) {
            a += __shfl_xor_sync(0xffffffffu, a, off);
            b += __shfl_xor_sync(0xffffffffu, b, off);
        }
        if (lane == 0) { g_el1[warp * 4 + h] = a; g_er1[warp * 4 + h] = b; }
    }
}

// ---------------- per-node attention logits, layer 2 (warp per node) ----------------
__global__ void att2_kernel(const float* __restrict__ al2, const float* __restrict__ ar2)
{
    int warp = (blockIdx.x * blockDim.x + threadIdx.x) >> 5;
    int lane = threadIdx.x & 31;
    if (warp >= NN) return;
    const float* row = g_fs2 + (size_t)warp * C2;
    float a = 0.f, b = 0.f;
    if (lane < C2)      { float v = row[lane];      a  = v * al2[lane];      b  = v * ar2[lane]; }
    if (lane + 32 < C2) { float v = row[lane + 32]; a += v * al2[lane + 32]; b += v * ar2[lane + 32]; }
#pragma unroll
    for (int off = 16; off; off >>= 1) {
        a += __shfl_xor_sync(0xffffffffu, a, off);
        b += __shfl_xor_sync(0xffffffffu, b, off);
    }
    if (lane == 0) { g_el2[warp] = a; g_er2[warp] = b; }
}

// ---------------- CSR row pointers from sorted dst (binary search) ----------------
__global__ void rowptr_kernel(const int* __restrict__ dst)
{
    int n = blockIdx.x * blockDim.x + threadIdx.x;
    if (n > NN) return;
    int lo = 0, hi = NE;
    while (lo < hi) {
        int mid = (lo + hi) >> 1;
        if (dst[mid] < n) lo = mid + 1; else hi = mid;
    }
    g_rowptr[n] = lo;
}

// ---------------- layer-1 segment softmax + aggregation: WARP per dst node ----------------
// 8 warps/block, no __syncthreads. Lane owns floats [lane*8, lane*8+8) of the 256-wide
// (4 heads x 64) feature row; its head is lane>>3. Weights computed once per
// (edge,head) by the chunk-owning lane, staged in per-warp smem.
__global__ void agg1_kernel(const int* __restrict__ src, const float* __restrict__ b1)
{
    __shared__ float4 smw[8][32];
    __shared__ int    smsrc[8][32];

    const int w    = threadIdx.x >> 5;
    const int lane = threadIdx.x & 31;
    const int n    = blockIdx.x * 8 + w;
    const int s = g_rowptr[n];
    const int e = g_rowptr[n + 1];
    const float4 er = *reinterpret_cast<const float4*>(g_er1 + n * 4);

    // pass 1: per-head max
    float4 mx = make_float4(-1e30f, -1e30f, -1e30f, -1e30f);
    for (int base = s; base < e; base += 32) {
        int j = base + lane;
        if (j < e) {
            int sj = src[j];
            float4 el = *reinterpret_cast<const float4*>(g_el1 + sj * 4);
            float v;
            v = el.x + er.x; v = v > 0.f ? v : 0.2f * v; mx.x = fmaxf(mx.x, v);
            v = el.y + er.y; v = v > 0.f ? v : 0.2f * v; mx.y = fmaxf(mx.y, v);
            v = el.z + er.z; v = v > 0.f ? v : 0.2f * v; mx.z = fmaxf(mx.z, v);
            v = el.w + er.w; v = v > 0.f ? v : 0.2f * v; mx.w = fmaxf(mx.w, v);
        }
    }
#pragma unroll
    for (int off = 16; off; off >>= 1) {
        mx.x = fmaxf(mx.x, __shfl_xor_sync(0xffffffffu, mx.x, off));
        mx.y = fmaxf(mx.y, __shfl_xor_sync(0xffffffffu, mx.y, off));
        mx.z = fmaxf(mx.z, __shfl_xor_sync(0xffffffffu, mx.z, off));
        mx.w = fmaxf(mx.w, __shfl_xor_sync(0xffffffffu, mx.w, off));
    }

    const int h = lane >> 3;
    float acc[8] = {0.f, 0.f, 0.f, 0.f, 0.f, 0.f, 0.f, 0.f};
    float den = 0.f;

    for (int base = s; base < e; base += 32) {
        int cnt = min(32, e - base);
        if (lane < cnt) {
            int sj = src[base + lane];
            float4 el = *reinterpret_cast<const float4*>(g_el1 + sj * 4);
            float4 wv; float v;
            v = el.x + er.x; v = v > 0.f ? v : 0.2f * v; wv.x = __expf(v - mx.x);
            v = el.y + er.y; v = v > 0.f ? v : 0.2f * v; wv.y = __expf(v - mx.y);
            v = el.z + er.z; v = v > 0.f ? v : 0.2f * v; wv.z = __expf(v - mx.z);
            v = el.w + er.w; v = v > 0.f ? v : 0.2f * v; wv.w = __expf(v - mx.w);
            smw[w][lane]   = wv;
            smsrc[w][lane] = sj;
        }
        __syncwarp();
#pragma unroll 2
        for (int jj = 0; jj < cnt; ++jj) {
            float wt = reinterpret_cast<const float*>(&smw[w][jj])[h];
            int  sj  = smsrc[w][jj];
            den += wt;
            const float4* fr = reinterpret_cast<const float4*>(g_fs1 + (size_t)sj * 256) + lane * 2;
            float4 f0 = fr[0], f1 = fr[1];
            acc[0] = fmaf(wt, f0.x, acc[0]); acc[1] = fmaf(wt, f0.y, acc[1]);
            acc[2] = fmaf(wt, f0.z, acc[2]); acc[3] = fmaf(wt, f0.w, acc[3]);
            acc[4] = fmaf(wt, f1.x, acc[4]); acc[5] = fmaf(wt, f1.y, acc[5]);
            acc[6] = fmaf(wt, f1.z, acc[6]); acc[7] = fmaf(wt, f1.w, acc[7]);
        }
        __syncwarp();
    }

    float rden = (e > s) ? 1.f / den : 0.f;
    float4 bb0 = *reinterpret_cast<const float4*>(b1 + lane * 8);
    float4 bb1 = *reinterpret_cast<const float4*>(b1 + lane * 8 + 4);
    float4 o0, o1;
    o0.x = fmaxf(acc[0] * rden + bb0.x, 0.f); o0.y = fmaxf(acc[1] * rden + bb0.y, 0.f);
    o0.z = fmaxf(acc[2] * rden + bb0.z, 0.f); o0.w = fmaxf(acc[3] * rden + bb0.w, 0.f);
    o1.x = fmaxf(acc[4] * rden + bb1.x, 0.f); o1.y = fmaxf(acc[5] * rden + bb1.y, 0.f);
    o1.z = fmaxf(acc[6] * rden + bb1.z, 0.f); o1.w = fmaxf(acc[7] * rden + bb1.w, 0.f);
    float* drow = g_h2 + (size_t)n * 256 + lane * 8;
    *reinterpret_cast<float4*>(drow)     = o0;
    *reinterpret_cast<float4*>(drow + 4) = o1;
}

// ---------------- layer-2 segment softmax + aggregation: WARP per dst node ----------------
__global__ void agg2_kernel(const int* __restrict__ src, const float* __restrict__ b2,
                            float* __restrict__ out)
{
    const int w    = threadIdx.x >> 5;
    const int lane = threadIdx.x & 31;
    const int n    = blockIdx.x * 8 + w;
    const int s = g_rowptr[n];
    const int e = g_rowptr[n + 1];
    const float ern = g_er2[n];

    float mx = -1e30f;
    for (int base = s; base < e; base += 32) {
        int j = base + lane;
        if (j < e) {
            float v = g_el2[src[j]] + ern;
            v = v > 0.f ? v : 0.2f * v;
            mx = fmaxf(mx, v);
        }
    }
#pragma unroll
    for (int off = 16; off; off >>= 1)
        mx = fmaxf(mx, __shfl_xor_sync(0xffffffffu, mx, off));

    float acc0 = 0.f, acc1 = 0.f, den = 0.f;
    for (int base = s; base < e; base += 32) {
        int cnt = min(32, e - base);
        float wv = 0.f; int sjv = 0;
        if (lane < cnt) {
            sjv = src[base + lane];
            float v = g_el2[sjv] + ern;
            v = v > 0.f ? v : 0.2f * v;
            wv = __expf(v - mx);
        }
#pragma unroll 2
        for (int jj = 0; jj < cnt; ++jj) {
            float wt = __shfl_sync(0xffffffffu, wv, jj);
            int  sj  = __shfl_sync(0xffffffffu, sjv, jj);
            den += wt;
            const float* fr = g_fs2 + (size_t)sj * C2;
            acc0 = fmaf(wt, fr[lane], acc0);
            if (lane < C2 - 32) acc1 = fmaf(wt, fr[lane + 32], acc1);
        }
    }

    float rden = (e > s) ? 1.f / den : 0.f;
    float* orow = out + (size_t)n * C2;
    orow[lane] = acc0 * rden + b2[lane];
    if (lane < C2 - 32) orow[lane + 32] = acc1 * rden + b2[lane + 32];
}

// ---------------- launch ----------------
extern "C" void kernel_launch(void* const* d_in, const int* in_sizes, int n_in,
                              void* d_out, int out_size)
{
    const float* x   = (const float*)d_in[0];
    const float* W1  = (const float*)d_in[1];
    const float* al1 = (const float*)d_in[2];
    const float* ar1 = (const float*)d_in[3];
    const float* b1  = (const float*)d_in[4];
    const float* W2  = (const float*)d_in[5];
    const float* al2 = (const float*)d_in[6];
    const float* ar2 = (const float*)d_in[7];
    const float* b2  = (const float*)d_in[8];
    const int*   src = (const int*)d_in[9];
    const int*   dst = (const int*)d_in[10];
    float* out = (float*)d_out;

    (void)in_sizes; (void)n_in; (void)out_size;

    rowptr_kernel<<<(NN + 1 + 255) / 256, 256>>>(dst);

    // Layer 1
    {
        float* fs1; cudaGetSymbolAddress((void**)&fs1, g_fs1);
        dim3 grid(4, (NN + 127) / 128);
        sgemm_kernel<256, 256, true><<<grid, 256>>>(x, W1, fs1, NN);
    }
    att1_kernel<<<(NN + 7) / 8, 256>>>(al1, ar1);
    agg1_kernel<<<NN / 8, 256>>>(src, b1);

    // Layer 2
    {
        float* h2;  cudaGetSymbolAddress((void**)&h2, g_h2);
        float* fs2; cudaGetSymbolAddress((void**)&fs2, g_fs2);
        dim3 grid(1, (NN + 127) / 128);
        sgemm_kernel<C2, 256, false><<<grid, 256>>>(h2, W2, fs2, NN);
    }
    att2_kernel<<<(NN + 7) / 8, 256>>>(al2, ar2);
    agg2_kernel<<<NN / 8, 256>>>(src, b2, out);
}

// round 4
// speedup vs baseline: 1.8687x; 1.3304x over previous
#include <cuda_runtime.h>
#include <cuda_bf16.h>
#include <cstdint>

#define NN  50000
#define NE  800000
#define NN_PAD 50048              // 391 * 128
#define FIN 256
#define H1  4
#define D1  64
#define C2  47

// ---------------- scratch (device globals; no allocation allowed) ----------------
__device__ __align__(16) float g_fs1[(size_t)NN * FIN];
__device__ __align__(16) float g_h2 [(size_t)NN * FIN];
__device__ __align__(16) float g_el1[NN * H1];
__device__ __align__(16) float g_er1[NN * H1];
__device__ __align__(16) float g_fs2[(size_t)NN * C2];
__device__ __align__(16) float g_el2[NN];
__device__ __align__(16) float g_er2[NN];
__device__ __align__(16) int   g_rowptr[NN + 1];
// bf16 hi/lo split of W1, transposed to [N,K]
__device__ __align__(16) __nv_bfloat16 g_w1hi[256 * 256];
__device__ __align__(16) __nv_bfloat16 g_w1lo[256 * 256];

// ================= warp-level MMA helpers (arch-agnostic PTX, sm_80+) =================
__device__ __forceinline__ uint32_t smem_to_u32(const void* p) {
    uint32_t a;
    asm("{ .reg .u64 t; cvta.to.shared.u64 t, %1; cvt.u32.u64 %0, t; }" : "=r"(a) : "l"(p));
    return a;
}
__device__ __forceinline__ void ldsm_x4(uint32_t addr, uint32_t r[4]) {
    asm volatile("ldmatrix.sync.aligned.m8n8.x4.shared.b16 {%0,%1,%2,%3}, [%4];"
                 : "=r"(r[0]), "=r"(r[1]), "=r"(r[2]), "=r"(r[3]) : "r"(addr));
}
__device__ __forceinline__ void ldsm_x2(uint32_t addr, uint32_t r[2]) {
    asm volatile("ldmatrix.sync.aligned.m8n8.x2.shared.b16 {%0,%1}, [%2];"
                 : "=r"(r[0]), "=r"(r[1]) : "r"(addr));
}
__device__ __forceinline__ void mma_bf16(float c[4], const uint32_t a[4], const uint32_t b[2]) {
    asm volatile("mma.sync.aligned.m16n8k16.row.col.f32.bf16.bf16.f32 "
                 "{%0,%1,%2,%3}, {%4,%5,%6,%7}, {%8,%9}, {%0,%1,%2,%3};"
                 : "+f"(c[0]), "+f"(c[1]), "+f"(c[2]), "+f"(c[3])
                 : "r"(a[0]), "r"(a[1]), "r"(a[2]), "r"(a[3]), "r"(b[0]), "r"(b[1]));
}
__device__ __forceinline__ uint32_t pack_bf16(__nv_bfloat16 a, __nv_bfloat16 b) {
    uint32_t lo = *reinterpret_cast<unsigned short*>(&a);
    uint32_t hi = *reinterpret_cast<unsigned short*>(&b);
    return lo | (hi << 16);
}

// W1[k,n] -> g_w1{hi,lo}[n,k] (transposed, hi/lo split). Tiny: 64K elems.
__global__ void w1split_kernel(const float* __restrict__ W1)
{
    int idx = blockIdx.x * blockDim.x + threadIdx.x;
    if (idx >= 256 * 256) return;
    int n = idx & 255, k = idx >> 8;
    float f = W1[(size_t)k * 256 + n];
    __nv_bfloat16 h = __float2bfloat16(f);
    __nv_bfloat16 l = __float2bfloat16(f - __bfloat162float(h));
    g_w1hi[(size_t)n * 256 + k] = h;
    g_w1lo[(size_t)n * 256 + k] = l;
}

// ================= GEMM1: bf16 3-term mma.sync, tile M128 x N64, K=256 in smem =================
#define LDT 264                       // padded row stride in bf16 elems (528 B)
#define OFF_AHI 0
#define OFF_ALO (128 * LDT * 2)       // 67584
#define OFF_BHI (OFF_ALO + 128 * LDT * 2)
#define OFF_BLO (OFF_BHI + 64 * LDT * 2)
#define GEMM1_SMEM (OFF_BLO + 64 * LDT * 2)   // 202752 B

__global__ void __launch_bounds__(512, 1) gemm1_mma_kernel(const float* __restrict__ x,
                                                           float* __restrict__ C)
{
    extern __shared__ __align__(16) char dsm[];
    const uint32_t sb = smem_to_u32(dsm);
    const int tid  = threadIdx.x;
    const int lane = tid & 31;
    const int wid  = tid >> 5;               // 0..15
    const int row0 = blockIdx.y * 128;
    const int col0 = blockIdx.x * 64;

    __nv_bfloat16* Ah = reinterpret_cast<__nv_bfloat16*>(dsm + OFF_AHI);
    __nv_bfloat16* Al = reinterpret_cast<__nv_bfloat16*>(dsm + OFF_ALO);
    __nv_bfloat16* Bh = reinterpret_cast<__nv_bfloat16*>(dsm + OFF_BHI);
    __nv_bfloat16* Bl = reinterpret_cast<__nv_bfloat16*>(dsm + OFF_BLO);

    // ---- A: load fp32 x rows, split to bf16 hi/lo in smem ----
#pragma unroll
    for (int i = 0; i < 16; ++i) {
        int idx = tid + i * 512;              // 0..8191 = 128 rows x 64 float4
        int r = idx >> 6, q = (idx & 63) * 4;
        int gr = row0 + r;
        float4 v = make_float4(0.f, 0.f, 0.f, 0.f);
        if (gr < NN) v = *reinterpret_cast<const float4*>(x + (size_t)gr * 256 + q);
        __nv_bfloat16 hx = __float2bfloat16(v.x), hy = __float2bfloat16(v.y);
        __nv_bfloat16 hz = __float2bfloat16(v.z), hw = __float2bfloat16(v.w);
        __nv_bfloat16 lx = __float2bfloat16(v.x - __bfloat162float(hx));
        __nv_bfloat16 ly = __float2bfloat16(v.y - __bfloat162float(hy));
        __nv_bfloat16 lz = __float2bfloat16(v.z - __bfloat162float(hz));
        __nv_bfloat16 lw = __float2bfloat16(v.w - __bfloat162float(hw));
        uint2 ph = make_uint2(pack_bf16(hx, hy), pack_bf16(hz, hw));
        uint2 pl = make_uint2(pack_bf16(lx, ly), pack_bf16(lz, lw));
        *reinterpret_cast<uint2*>(Ah + r * LDT + q) = ph;
        *reinterpret_cast<uint2*>(Al + r * LDT + q) = pl;
    }
    // ---- B: copy pre-split bf16 W1^T rows [64 x 256] ----
#pragma unroll
    for (int i = 0; i < 4; ++i) {
        int idx = tid + i * 512;              // 0..2047 = 64 rows x 32 uint4
        int r = idx >> 5, c8 = (idx & 31) * 8;
        size_t go = (size_t)(col0 + r) * 256 + c8;
        *reinterpret_cast<uint4*>(Bh + r * LDT + c8) = *reinterpret_cast<const uint4*>(g_w1hi + go);
        *reinterpret_cast<uint4*>(Bl + r * LDT + c8) = *reinterpret_cast<const uint4*>(g_w1lo + go);
    }
    __syncthreads();

    // ---- warp tiles: 8 (M) x 2 (N); warp tile m16 x n32 ----
    const int wm = wid >> 1;                  // 0..7
    const int wn = wid & 1;                   // 0..1
    const int m0 = wm * 16;
    const int n0 = wn * 32;

    uint32_t aAh = sb + OFF_AHI + (uint32_t)((m0 + (lane & 15)) * LDT + ((lane >> 4) & 1) * 8) * 2;
    uint32_t aAl = aAh + (OFF_ALO - OFF_AHI);
    uint32_t aBh = sb + OFF_BHI + (uint32_t)((n0 + (lane & 7)) * LDT + ((lane >> 3) & 1) * 8) * 2;
    uint32_t aBl = aBh + (OFF_BLO - OFF_BHI);

    float c[4][4];
#pragma unroll
    for (int g = 0; g < 4; ++g)
#pragma unroll
        for (int q = 0; q < 4; ++q) c[g][q] = 0.f;

#pragma unroll
    for (int ks = 0; ks < 16; ++ks) {
        uint32_t fAh[4], fAl[4];
        ldsm_x4(aAh, fAh);
        ldsm_x4(aAl, fAl);
#pragma unroll
        for (int g = 0; g < 4; ++g) {
            uint32_t bh[2], bl[2];
            ldsm_x2(aBh + g * 8 * LDT * 2, bh);
            ldsm_x2(aBl + g * 8 * LDT * 2, bl);
            mma_bf16(c[g], fAh, bh);
            mma_bf16(c[g], fAl, bh);
            mma_bf16(c[g], fAh, bl);
        }
        aAh += 32; aAl += 32; aBh += 32; aBl += 32;   // advance k by 16 bf16
    }

    // ---- epilogue ----
    int r0 = row0 + m0 + (lane >> 2);
    int cb = col0 + n0 + 2 * (lane & 3);
#pragma unroll
    for (int g = 0; g < 4; ++g) {
        if (r0 < NN)
            *reinterpret_cast<float2*>(C + (size_t)r0 * 256 + cb + g * 8) = make_float2(c[g][0], c[g][1]);
        if (r0 + 8 < NN)
            *reinterpret_cast<float2*>(C + (size_t)(r0 + 8) * 256 + cb + g * 8) = make_float2(c[g][2], c[g][3]);
    }
}

// ---------------- packed fp32x2 FMA ----------------
__device__ __forceinline__ void fma_x2(float2& d, const float2& a, const float2& b)
{
    asm("fma.rn.f32x2 %0, %1, %2, %0;"
        : "+l"(reinterpret_cast<unsigned long long&>(d))
        : "l"(reinterpret_cast<const unsigned long long&>(a)),
          "l"(reinterpret_cast<const unsigned long long&>(b)));
}

// ---------------- SGEMM (layer 2): C[M,N]=A[M,K]*B[K,N], BM=128 BN=64 BK=16 ----------------
template <int N, int K, bool VEC>
__global__ void sgemm_kernel(const float* __restrict__ A, const float* __restrict__ B,
                             float* __restrict__ C, int M)
{
    __shared__ float2 As2[16][130];
    __shared__ float  Bs[16][64];
    const int tid = threadIdx.x;
    const int tx  = tid & 15;
    const int ty  = tid >> 4;
    const int row0 = blockIdx.y * 128;
    const int col0 = blockIdx.x * 64;

    float2 acc[8][2];
#pragma unroll
    for (int i = 0; i < 8; ++i) { acc[i][0] = make_float2(0.f, 0.f); acc[i][1] = make_float2(0.f, 0.f); }

    for (int k0 = 0; k0 < K; k0 += 16) {
#pragma unroll
        for (int i = 0; i < 2; ++i) {
            int idx = tid + i * 256;
            int r = idx >> 2, q = idx & 3;
            int gr = row0 + r;
            float4 v = make_float4(0.f, 0.f, 0.f, 0.f);
            if (gr < M) v = *reinterpret_cast<const float4*>(A + (size_t)gr * K + k0 + q * 4);
            As2[q * 4 + 0][r] = make_float2(v.x, v.x);
            As2[q * 4 + 1][r] = make_float2(v.y, v.y);
            As2[q * 4 + 2][r] = make_float2(v.z, v.z);
            As2[q * 4 + 3][r] = make_float2(v.w, v.w);
        }
        if (VEC) {
            int kk = tid >> 4, c = (tid & 15) * 4;
            float4 v = *reinterpret_cast<const float4*>(B + (size_t)(k0 + kk) * N + col0 + c);
            *reinterpret_cast<float4*>(&Bs[kk][c]) = v;
        } else {
#pragma unroll
            for (int i = 0; i < 4; ++i) {
                int e = tid + i * 256;
                int kk = e >> 6, c = e & 63;
                int gc = col0 + c;
                Bs[kk][c] = (gc < N) ? B[(size_t)(k0 + kk) * N + gc] : 0.f;
            }
        }
        __syncthreads();
#pragma unroll
        for (int kk = 0; kk < 16; ++kk) {
            float2 ra[8];
            const float4* pa = reinterpret_cast<const float4*>(&As2[kk][ty * 8]);
#pragma unroll
            for (int q = 0; q < 4; ++q) {
                float4 t = pa[q];
                ra[q * 2 + 0] = make_float2(t.x, t.y);
                ra[q * 2 + 1] = make_float2(t.z, t.w);
            }
            float4 bq = *reinterpret_cast<const float4*>(&Bs[kk][tx * 4]);
            float2 rb0 = make_float2(bq.x, bq.y);
            float2 rb1 = make_float2(bq.z, bq.w);
#pragma unroll
            for (int i = 0; i < 8; ++i) {
                fma_x2(acc[i][0], ra[i], rb0);
                fma_x2(acc[i][1], ra[i], rb1);
            }
        }
        __syncthreads();
    }
#pragma unroll
    for (int i = 0; i < 8; ++i) {
        int gr = row0 + ty * 8 + i;
        if (gr >= M) continue;
        if (VEC) {
            *reinterpret_cast<float2*>(C + (size_t)gr * N + col0 + tx * 4)     = acc[i][0];
            *reinterpret_cast<float2*>(C + (size_t)gr * N + col0 + tx * 4 + 2) = acc[i][1];
        } else {
            int gc = col0 + tx * 4;
            if (gc + 0 < N) C[(size_t)gr * N + gc + 0] = acc[i][0].x;
            if (gc + 1 < N) C[(size_t)gr * N + gc + 1] = acc[i][0].y;
            if (gc + 2 < N) C[(size_t)gr * N + gc + 2] = acc[i][1].x;
            if (gc + 3 < N) C[(size_t)gr * N + gc + 3] = acc[i][1].y;
        }
    }
}

// ---------------- per-node attention logits, layer 1 (warp per node) ----------------
__global__ void att1_kernel(const float* __restrict__ al, const float* __restrict__ ar)
{
    int warp = (blockIdx.x * blockDim.x + threadIdx.x) >> 5;
    int lane = threadIdx.x & 31;
    if (warp >= NN) return;
    const float* row = g_fs1 + (size_t)warp * 256;
#pragma unroll
    for (int h = 0; h < 4; ++h) {
        float v1 = row[h * 64 + lane];
        float v2 = row[h * 64 + 32 + lane];
        float a = v1 * al[h * 64 + lane] + v2 * al[h * 64 + 32 + lane];
        float b = v1 * ar[h * 64 + lane] + v2 * ar[h * 64 + 32 + lane];
#pragma unroll
        for (int off = 16; off; off >>= 1) {
            a += __shfl_xor_sync(0xffffffffu, a, off);
            b += __shfl_xor_sync(0xffffffffu, b, off);
        }
        if (lane == 0) { g_el1[warp * 4 + h] = a; g_er1[warp * 4 + h] = b; }
    }
}

// ---------------- per-node attention logits, layer 2 (warp per node) ----------------
__global__ void att2_kernel(const float* __restrict__ al2, const float* __restrict__ ar2)
{
    int warp = (blockIdx.x * blockDim.x + threadIdx.x) >> 5;
    int lane = threadIdx.x & 31;
    if (warp >= NN) return;
    const float* row = g_fs2 + (size_t)warp * C2;
    float a = 0.f, b = 0.f;
    if (lane < C2)      { float v = row[lane];      a  = v * al2[lane];      b  = v * ar2[lane]; }
    if (lane + 32 < C2) { float v = row[lane + 32]; a += v * al2[lane + 32]; b += v * ar2[lane + 32]; }
#pragma unroll
    for (int off = 16; off; off >>= 1) {
        a += __shfl_xor_sync(0xffffffffu, a, off);
        b += __shfl_xor_sync(0xffffffffu, b, off);
    }
    if (lane == 0) { g_el2[warp] = a; g_er2[warp] = b; }
}

// ---------------- CSR row pointers from sorted dst ----------------
__global__ void rowptr_kernel(const int* __restrict__ dst)
{
    int n = blockIdx.x * blockDim.x + threadIdx.x;
    if (n > NN) return;
    int lo = 0, hi = NE;
    while (lo < hi) {
        int mid = (lo + hi) >> 1;
        if (dst[mid] < n) lo = mid + 1; else hi = mid;
    }
    g_rowptr[n] = lo;
}

// ---------------- layer-1 segment softmax + aggregation: WARP per dst node ----------------
__global__ void agg1_kernel(const int* __restrict__ src, const float* __restrict__ b1)
{
    __shared__ float4 smw[8][32];
    __shared__ int    smsrc[8][32];

    const int w    = threadIdx.x >> 5;
    const int lane = threadIdx.x & 31;
    const int n    = blockIdx.x * 8 + w;
    const int s = g_rowptr[n];
    const int e = g_rowptr[n + 1];
    const float4 er = *reinterpret_cast<const float4*>(g_er1 + n * 4);

    float4 mx = make_float4(-1e30f, -1e30f, -1e30f, -1e30f);
    for (int base = s; base < e; base += 32) {
        int j = base + lane;
        if (j < e) {
            int sj = src[j];
            float4 el = *reinterpret_cast<const float4*>(g_el1 + sj * 4);
            float v;
            v = el.x + er.x; v = v > 0.f ? v : 0.2f * v; mx.x = fmaxf(mx.x, v);
            v = el.y + er.y; v = v > 0.f ? v : 0.2f * v; mx.y = fmaxf(mx.y, v);
            v = el.z + er.z; v = v > 0.f ? v : 0.2f * v; mx.z = fmaxf(mx.z, v);
            v = el.w + er.w; v = v > 0.f ? v : 0.2f * v; mx.w = fmaxf(mx.w, v);
        }
    }
#pragma unroll
    for (int off = 16; off; off >>= 1) {
        mx.x = fmaxf(mx.x, __shfl_xor_sync(0xffffffffu, mx.x, off));
        mx.y = fmaxf(mx.y, __shfl_xor_sync(0xffffffffu, mx.y, off));
        mx.z = fmaxf(mx.z, __shfl_xor_sync(0xffffffffu, mx.z, off));
        mx.w = fmaxf(mx.w, __shfl_xor_sync(0xffffffffu, mx.w, off));
    }

    const int h = lane >> 3;
    float acc[8] = {0.f, 0.f, 0.f, 0.f, 0.f, 0.f, 0.f, 0.f};
    float den = 0.f;

    for (int base = s; base < e; base += 32) {
        int cnt = min(32, e - base);
        if (lane < cnt) {
            int sj = src[base + lane];
            float4 el = *reinterpret_cast<const float4*>(g_el1 + sj * 4);
            float4 wv; float v;
            v = el.x + er.x; v = v > 0.f ? v : 0.2f * v; wv.x = __expf(v - mx.x);
            v = el.y + er.y; v = v > 0.f ? v : 0.2f * v; wv.y = __expf(v - mx.y);
            v = el.z + er.z; v = v > 0.f ? v : 0.2f * v; wv.z = __expf(v - mx.z);
            v = el.w + er.w; v = v > 0.f ? v : 0.2f * v; wv.w = __expf(v - mx.w);
            smw[w][lane]   = wv;
            smsrc[w][lane] = sj;
        }
        __syncwarp();
#pragma unroll 2
        for (int jj = 0; jj < cnt; ++jj) {
            float wt = reinterpret_cast<const float*>(&smw[w][jj])[h];
            int  sj  = smsrc[w][jj];
            den += wt;
            const float4* fr = reinterpret_cast<const float4*>(g_fs1 + (size_t)sj * 256) + lane * 2;
            float4 f0 = fr[0], f1 = fr[1];
            acc[0] = fmaf(wt, f0.x, acc[0]); acc[1] = fmaf(wt, f0.y, acc[1]);
            acc[2] = fmaf(wt, f0.z, acc[2]); acc[3] = fmaf(wt, f0.w, acc[3]);
            acc[4] = fmaf(wt, f1.x, acc[4]); acc[5] = fmaf(wt, f1.y, acc[5]);
            acc[6] = fmaf(wt, f1.z, acc[6]); acc[7] = fmaf(wt, f1.w, acc[7]);
        }
        __syncwarp();
    }

    float rden = (e > s) ? 1.f / den : 0.f;
    float4 bb0 = *reinterpret_cast<const float4*>(b1 + lane * 8);
    float4 bb1 = *reinterpret_cast<const float4*>(b1 + lane * 8 + 4);
    float4 o0, o1;
    o0.x = fmaxf(acc[0] * rden + bb0.x, 0.f); o0.y = fmaxf(acc[1] * rden + bb0.y, 0.f);
    o0.z = fmaxf(acc[2] * rden + bb0.z, 0.f); o0.w = fmaxf(acc[3] * rden + bb0.w, 0.f);
    o1.x = fmaxf(acc[4] * rden + bb1.x, 0.f); o1.y = fmaxf(acc[5] * rden + bb1.y, 0.f);
    o1.z = fmaxf(acc[6] * rden + bb1.z, 0.f); o1.w = fmaxf(acc[7] * rden + bb1.w, 0.f);
    float* drow = g_h2 + (size_t)n * 256 + lane * 8;
    *reinterpret_cast<float4*>(drow)     = o0;
    *reinterpret_cast<float4*>(drow + 4) = o1;
}

// ---------------- layer-2 segment softmax + aggregation: WARP per dst node ----------------
__global__ void agg2_kernel(const int* __restrict__ src, const float* __restrict__ b2,
                            float* __restrict__ out)
{
    const int w    = threadIdx.x >> 5;
    const int lane = threadIdx.x & 31;
    const int n    = blockIdx.x * 8 + w;
    const int s = g_rowptr[n];
    const int e = g_rowptr[n + 1];
    const float ern = g_er2[n];

    float mx = -1e30f;
    for (int base = s; base < e; base += 32) {
        int j = base + lane;
        if (j < e) {
            float v = g_el2[src[j]] + ern;
            v = v > 0.f ? v : 0.2f * v;
            mx = fmaxf(mx, v);
        }
    }
#pragma unroll
    for (int off = 16; off; off >>= 1)
        mx = fmaxf(mx, __shfl_xor_sync(0xffffffffu, mx, off));

    float acc0 = 0.f, acc1 = 0.f, den = 0.f;
    for (int base = s; base < e; base += 32) {
        int cnt = min(32, e - base);
        float wv = 0.f; int sjv = 0;
        if (lane < cnt) {
            sjv = src[base + lane];
            float v = g_el2[sjv] + ern;
            v = v > 0.f ? v : 0.2f * v;
            wv = __expf(v - mx);
        }
#pragma unroll 2
        for (int jj = 0; jj < cnt; ++jj) {
            float wt = __shfl_sync(0xffffffffu, wv, jj);
            int  sj  = __shfl_sync(0xffffffffu, sjv, jj);
            den += wt;
            const float* fr = g_fs2 + (size_t)sj * C2;
            acc0 = fmaf(wt, fr[lane], acc0);
            if (lane < C2 - 32) acc1 = fmaf(wt, fr[lane + 32], acc1);
        }
    }

    float rden = (e > s) ? 1.f / den : 0.f;
    float* orow = out + (size_t)n * C2;
    orow[lane] = acc0 * rden + b2[lane];
    if (lane < C2 - 32) orow[lane + 32] = acc1 * rden + b2[lane + 32];
}

// ---------------- launch ----------------
extern "C" void kernel_launch(void* const* d_in, const int* in_sizes, int n_in,
                              void* d_out, int out_size)
{
    const float* x   = (const float*)d_in[0];
    const float* W1  = (const float*)d_in[1];
    const float* al1 = (const float*)d_in[2];
    const float* ar1 = (const float*)d_in[3];
    const float* b1  = (const float*)d_in[4];
    const float* W2  = (const float*)d_in[5];
    const float* al2 = (const float*)d_in[6];
    const float* ar2 = (const float*)d_in[7];
    const float* b2  = (const float*)d_in[8];
    const int*   src = (const int*)d_in[9];
    const int*   dst = (const int*)d_in[10];
    float* out = (float*)d_out;

    (void)in_sizes; (void)n_in; (void)out_size;

    cudaFuncSetAttribute(gemm1_mma_kernel,
                         cudaFuncAttributeMaxDynamicSharedMemorySize, GEMM1_SMEM);

    rowptr_kernel<<<(NN + 1 + 255) / 256, 256>>>(dst);

    // Layer 1: tensor-core GEMM (bf16 3-term split), in-kernel A conversion
    w1split_kernel<<<256, 256>>>(W1);
    {
        float* fs1; cudaGetSymbolAddress((void**)&fs1, g_fs1);
        dim3 grid(4, NN_PAD / 128);
        gemm1_mma_kernel<<<grid, 512, GEMM1_SMEM>>>(x, fs1);
    }
    att1_kernel<<<(NN + 7) / 8, 256>>>(al1, ar1);
    agg1_kernel<<<NN / 8, 256>>>(src, b1);

    // Layer 2
    {
        float* h2;  cudaGetSymbolAddress((void**)&h2, g_h2);
        float* fs2; cudaGetSymbolAddress((void**)&fs2, g_fs2);
        dim3 grid(1, (NN + 127) / 128);
        sgemm_kernel<C2, 256, false><<<grid, 256>>>(h2, W2, fs2, NN);
    }
    att2_kernel<<<(NN + 7) / 8, 256>>>(al2, ar2);
    agg2_kernel<<<NN / 8, 256>>>(src, b2, out);
}

// round 5
// speedup vs baseline: 2.4284x; 1.2995x over previous
#include <cuda_runtime.h>
#include <cuda_bf16.h>
#include <cstdint>

#define NN  50000
#define NE  800000
#define NN_PAD 50048              // 391 * 128
#define FIN 256
#define H1  4
#define D1  64
#define C2  47

// ---------------- scratch (device globals; no allocation allowed) ----------------
__device__ __align__(16) float g_fs1[(size_t)NN * FIN];
__device__ __align__(16) float g_h2 [(size_t)NN * FIN];
__device__ __align__(16) float g_el1[NN * H1];
__device__ __align__(16) float g_er1[NN * H1];
__device__ __align__(16) float g_fs2[(size_t)NN * C2];
__device__ __align__(16) float g_el2[NN];
__device__ __align__(16) float g_er2[NN];
__device__ __align__(16) int   g_rowptr[NN + 1];
// bf16 hi/lo splits of W1^T [256,256] and W2^T padded [64,256]
__device__ __align__(16) __nv_bfloat16 g_w1hi[256 * 256];
__device__ __align__(16) __nv_bfloat16 g_w1lo[256 * 256];
__device__ __align__(16) __nv_bfloat16 g_w2hi[64 * 256];
__device__ __align__(16) __nv_bfloat16 g_w2lo[64 * 256];

// ================= warp-level MMA helpers (arch-agnostic PTX, sm_80+) =================
__device__ __forceinline__ uint32_t smem_to_u32(const void* p) {
    uint32_t a;
    asm("{ .reg .u64 t; cvta.to.shared.u64 t, %1; cvt.u32.u64 %0, t; }" : "=r"(a) : "l"(p));
    return a;
}
__device__ __forceinline__ void ldsm_x4(uint32_t addr, uint32_t r[4]) {
    asm volatile("ldmatrix.sync.aligned.m8n8.x4.shared.b16 {%0,%1,%2,%3}, [%4];"
                 : "=r"(r[0]), "=r"(r[1]), "=r"(r[2]), "=r"(r[3]) : "r"(addr));
}
__device__ __forceinline__ void ldsm_x2(uint32_t addr, uint32_t r[2]) {
    asm volatile("ldmatrix.sync.aligned.m8n8.x2.shared.b16 {%0,%1}, [%2];"
                 : "=r"(r[0]), "=r"(r[1]) : "r"(addr));
}
__device__ __forceinline__ void mma_bf16(float c[4], const uint32_t a[4], const uint32_t b[2]) {
    asm volatile("mma.sync.aligned.m16n8k16.row.col.f32.bf16.bf16.f32 "
                 "{%0,%1,%2,%3}, {%4,%5,%6,%7}, {%8,%9}, {%0,%1,%2,%3};"
                 : "+f"(c[0]), "+f"(c[1]), "+f"(c[2]), "+f"(c[3])
                 : "r"(a[0]), "r"(a[1]), "r"(a[2]), "r"(a[3]), "r"(b[0]), "r"(b[1]));
}
__device__ __forceinline__ uint32_t pack_bf16(__nv_bfloat16 a, __nv_bfloat16 b) {
    uint32_t lo = *reinterpret_cast<unsigned short*>(&a);
    uint32_t hi = *reinterpret_cast<unsigned short*>(&b);
    return lo | (hi << 16);
}

// W1[k,n] -> g_w1{hi,lo}[n,k]; W2[k,n] -> g_w2{hi,lo}[n,k] zero-padded to 64 rows.
__global__ void wsplit_kernel(const float* __restrict__ W1, const float* __restrict__ W2)
{
    int idx = blockIdx.x * blockDim.x + threadIdx.x;
    if (idx < 65536) {
        int n = idx & 255, k = idx >> 8;
        float f = W1[(size_t)k * 256 + n];
        __nv_bfloat16 h = __float2bfloat16(f);
        __nv_bfloat16 l = __float2bfloat16(f - __bfloat162float(h));
        g_w1hi[(size_t)n * 256 + k] = h;
        g_w1lo[(size_t)n * 256 + k] = l;
    } else if (idx < 65536 + 16384) {
        int j = idx - 65536;
        int n = j >> 8, k = j & 255;
        float f = (n < C2) ? W2[(size_t)k * C2 + n] : 0.f;
        __nv_bfloat16 h = __float2bfloat16(f);
        __nv_bfloat16 l = __float2bfloat16(f - __bfloat162float(h));
        g_w2hi[(size_t)n * 256 + k] = h;
        g_w2lo[(size_t)n * 256 + k] = l;
    }
}

// ================= fused GEMM + attention-logit kernels =================
#define LDT 264                       // padded row stride in bf16 elems (528 B)
#define OFF_AHI 0
#define OFF_ALO (128 * LDT * 2)
#define OFF_BHI (OFF_ALO + 128 * LDT * 2)
#define OFF_BLO (OFF_BHI + 64 * LDT * 2)
#define GEMM_SMEM (OFF_BLO + 64 * LDT * 2)   // 202752 B dynamic

// ---- load 128 fp32 rows of src (stride 256) into Ah/Al hi/lo smem tiles ----
__device__ __forceinline__ void load_A_split(const float* __restrict__ src, int row0,
                                             __nv_bfloat16* Ah, __nv_bfloat16* Al, int tid)
{
#pragma unroll
    for (int i = 0; i < 16; ++i) {
        int idx = tid + i * 512;              // 0..8191 = 128 rows x 64 float4
        int r = idx >> 6, q = (idx & 63) * 4;
        int gr = row0 + r;
        float4 v = make_float4(0.f, 0.f, 0.f, 0.f);
        if (gr < NN) v = *reinterpret_cast<const float4*>(src + (size_t)gr * 256 + q);
        __nv_bfloat16 hx = __float2bfloat16(v.x), hy = __float2bfloat16(v.y);
        __nv_bfloat16 hz = __float2bfloat16(v.z), hw = __float2bfloat16(v.w);
        __nv_bfloat16 lx = __float2bfloat16(v.x - __bfloat162float(hx));
        __nv_bfloat16 ly = __float2bfloat16(v.y - __bfloat162float(hy));
        __nv_bfloat16 lz = __float2bfloat16(v.z - __bfloat162float(hz));
        __nv_bfloat16 lw = __float2bfloat16(v.w - __bfloat162float(hw));
        *reinterpret_cast<uint2*>(Ah + r * LDT + q) = make_uint2(pack_bf16(hx, hy), pack_bf16(hz, hw));
        *reinterpret_cast<uint2*>(Al + r * LDT + q) = make_uint2(pack_bf16(lx, ly), pack_bf16(lz, lw));
    }
}

// ---- load 64 bf16 rows (stride 256) into B smem tile ----
__device__ __forceinline__ void load_B(const __nv_bfloat16* __restrict__ srcH,
                                       const __nv_bfloat16* __restrict__ srcL,
                                       int rowoff, __nv_bfloat16* Bh, __nv_bfloat16* Bl, int tid)
{
#pragma unroll
    for (int i = 0; i < 4; ++i) {
        int idx = tid + i * 512;              // 0..2047 = 64 rows x 32 uint4
        int r = idx >> 5, c8 = (idx & 31) * 8;
        size_t go = (size_t)(rowoff + r) * 256 + c8;
        *reinterpret_cast<uint4*>(Bh + r * LDT + c8) = *reinterpret_cast<const uint4*>(srcH + go);
        *reinterpret_cast<uint4*>(Bl + r * LDT + c8) = *reinterpret_cast<const uint4*>(srcL + go);
    }
}

// ---- warp MMA over K=256, 3-term bf16 split; returns c[4][4] ----
__device__ __forceinline__ void mma_k256(uint32_t sb, int m0, int n0, float c[4][4])
{
#pragma unroll
    for (int g = 0; g < 4; ++g)
#pragma unroll
        for (int q = 0; q < 4; ++q) c[g][q] = 0.f;

    const int lane = threadIdx.x & 31;
    uint32_t aAh = sb + OFF_AHI + (uint32_t)((m0 + (lane & 15)) * LDT + ((lane >> 4) & 1) * 8) * 2;
    uint32_t aAl = aAh + (OFF_ALO - OFF_AHI);
    uint32_t aBh = sb + OFF_BHI + (uint32_t)((n0 + (lane & 7)) * LDT + ((lane >> 3) & 1) * 8) * 2;
    uint32_t aBl = aBh + (OFF_BLO - OFF_BHI);

#pragma unroll
    for (int ks = 0; ks < 16; ++ks) {
        uint32_t fAh[4], fAl[4];
        ldsm_x4(aAh, fAh);
        ldsm_x4(aAl, fAl);
#pragma unroll
        for (int g = 0; g < 4; ++g) {
            uint32_t bh[2], bl[2];
            ldsm_x2(aBh + g * 8 * LDT * 2, bh);
            ldsm_x2(aBl + g * 8 * LDT * 2, bl);
            mma_bf16(c[g], fAh, bh);
            mma_bf16(c[g], fAl, bh);
            mma_bf16(c[g], fAh, bl);
        }
        aAh += 32; aAl += 32; aBh += 32; aBl += 32;
    }
}

// ================= GEMM1 (x @ W1) + el1/er1, 4 head-tiles per CTA =================
__global__ void __launch_bounds__(512, 1) gemm1_mma_kernel(const float* __restrict__ x,
                                                           const float* __restrict__ al1,
                                                           const float* __restrict__ ar1)
{
    extern __shared__ __align__(16) char dsm[];
    __shared__ float als[256], ars[256];
    __shared__ float elp[2][128], erp[2][128];

    const uint32_t sb = smem_to_u32(dsm);
    const int tid  = threadIdx.x;
    const int lane = tid & 31;
    const int wid  = tid >> 5;
    const int wm = wid >> 1, wn = wid & 1;
    const int m0 = wm * 16, n0 = wn * 32;
    const int row0 = blockIdx.x * 128;

    __nv_bfloat16* Ah = reinterpret_cast<__nv_bfloat16*>(dsm + OFF_AHI);
    __nv_bfloat16* Al = reinterpret_cast<__nv_bfloat16*>(dsm + OFF_ALO);
    __nv_bfloat16* Bh = reinterpret_cast<__nv_bfloat16*>(dsm + OFF_BHI);
    __nv_bfloat16* Bl = reinterpret_cast<__nv_bfloat16*>(dsm + OFF_BLO);

    load_A_split(x, row0, Ah, Al, tid);
    if (tid < 256) { als[tid] = al1[tid]; ars[tid] = ar1[tid]; }

#pragma unroll 1
    for (int ct = 0; ct < 4; ++ct) {
        const int col0 = ct * 64;
        load_B(g_w1hi, g_w1lo, col0, Bh, Bl, tid);
        __syncthreads();

        float c[4][4];
        mma_k256(sb, m0, n0, c);

        // ---- store C + per-row attention partials for head ct ----
        const int r0 = row0 + m0 + (lane >> 2);
        const int cbl = n0 + 2 * (lane & 3);         // col within head tile
        float pel0 = 0.f, per0 = 0.f, pel8 = 0.f, per8 = 0.f;
#pragma unroll
        for (int g = 0; g < 4; ++g) {
            float a0 = als[col0 + cbl + g * 8], a1 = als[col0 + cbl + g * 8 + 1];
            float b0 = ars[col0 + cbl + g * 8], b1 = ars[col0 + cbl + g * 8 + 1];
            pel0 += c[g][0] * a0 + c[g][1] * a1;
            per0 += c[g][0] * b0 + c[g][1] * b1;
            pel8 += c[g][2] * a0 + c[g][3] * a1;
            per8 += c[g][2] * b0 + c[g][3] * b1;
            if (r0 < NN)
                *reinterpret_cast<float2*>(g_fs1 + (size_t)r0 * 256 + col0 + cbl + g * 8) =
                    make_float2(c[g][0], c[g][1]);
            if (r0 + 8 < NN)
                *reinterpret_cast<float2*>(g_fs1 + (size_t)(r0 + 8) * 256 + col0 + cbl + g * 8) =
                    make_float2(c[g][2], c[g][3]);
        }
        pel0 += __shfl_xor_sync(0xffffffffu, pel0, 1); pel0 += __shfl_xor_sync(0xffffffffu, pel0, 2);
        per0 += __shfl_xor_sync(0xffffffffu, per0, 1); per0 += __shfl_xor_sync(0xffffffffu, per0, 2);
        pel8 += __shfl_xor_sync(0xffffffffu, pel8, 1); pel8 += __shfl_xor_sync(0xffffffffu, pel8, 2);
        per8 += __shfl_xor_sync(0xffffffffu, per8, 1); per8 += __shfl_xor_sync(0xffffffffu, per8, 2);
        if ((lane & 3) == 0) {
            int rr = m0 + (lane >> 2);
            elp[wn][rr] = pel0; elp[wn][rr + 8] = pel8;
            erp[wn][rr] = per0; erp[wn][rr + 8] = per8;
        }
        __syncthreads();
        if (tid < 128) {
            int row = row0 + tid;
            if (row < NN) {
                g_el1[row * 4 + ct] = elp[0][tid] + elp[1][tid];
                g_er1[row * 4 + ct] = erp[0][tid] + erp[1][tid];
            }
        }
    }
}

// ================= GEMM2 (h2 @ W2) + el2/er2 =================
__global__ void __launch_bounds__(512, 1) gemm2_mma_kernel(const float* __restrict__ al2,
                                                           const float* __restrict__ ar2)
{
    extern __shared__ __align__(16) char dsm[];
    __shared__ float als[64], ars[64];
    __shared__ float elp[2][128], erp[2][128];

    const uint32_t sb = smem_to_u32(dsm);
    const int tid  = threadIdx.x;
    const int lane = tid & 31;
    const int wid  = tid >> 5;
    const int wm = wid >> 1, wn = wid & 1;
    const int m0 = wm * 16, n0 = wn * 32;
    const int row0 = blockIdx.x * 128;

    __nv_bfloat16* Ah = reinterpret_cast<__nv_bfloat16*>(dsm + OFF_AHI);
    __nv_bfloat16* Al = reinterpret_cast<__nv_bfloat16*>(dsm + OFF_ALO);
    __nv_bfloat16* Bh = reinterpret_cast<__nv_bfloat16*>(dsm + OFF_BHI);
    __nv_bfloat16* Bl = reinterpret_cast<__nv_bfloat16*>(dsm + OFF_BLO);

    load_A_split(g_h2, row0, Ah, Al, tid);
    if (tid < 64) {
        als[tid] = (tid < C2) ? al2[tid] : 0.f;
        ars[tid] = (tid < C2) ? ar2[tid] : 0.f;
    }
    load_B(g_w2hi, g_w2lo, 0, Bh, Bl, tid);
    __syncthreads();

    float c[4][4];
    mma_k256(sb, m0, n0, c);

    const int r0 = row0 + m0 + (lane >> 2);
    const int cbl = n0 + 2 * (lane & 3);
    float pel0 = 0.f, per0 = 0.f, pel8 = 0.f, per8 = 0.f;
#pragma unroll
    for (int g = 0; g < 4; ++g) {
        int cc = cbl + g * 8;
        float a0 = als[cc], a1 = als[cc + 1];
        float b0 = ars[cc], b1 = ars[cc + 1];
        pel0 += c[g][0] * a0 + c[g][1] * a1;
        per0 += c[g][0] * b0 + c[g][1] * b1;
        pel8 += c[g][2] * a0 + c[g][3] * a1;
        per8 += c[g][2] * b0 + c[g][3] * b1;
        if (r0 < NN) {
            if (cc < C2)     g_fs2[(size_t)r0 * C2 + cc]     = c[g][0];
            if (cc + 1 < C2) g_fs2[(size_t)r0 * C2 + cc + 1] = c[g][1];
        }
        if (r0 + 8 < NN) {
            if (cc < C2)     g_fs2[(size_t)(r0 + 8) * C2 + cc]     = c[g][2];
            if (cc + 1 < C2) g_fs2[(size_t)(r0 + 8) * C2 + cc + 1] = c[g][3];
        }
    }
    pel0 += __shfl_xor_sync(0xffffffffu, pel0, 1); pel0 += __shfl_xor_sync(0xffffffffu, pel0, 2);
    per0 += __shfl_xor_sync(0xffffffffu, per0, 1); per0 += __shfl_xor_sync(0xffffffffu, per0, 2);
    pel8 += __shfl_xor_sync(0xffffffffu, pel8, 1); pel8 += __shfl_xor_sync(0xffffffffu, pel8, 2);
    per8 += __shfl_xor_sync(0xffffffffu, per8, 1); per8 += __shfl_xor_sync(0xffffffffu, per8, 2);
    if ((lane & 3) == 0) {
        int rr = m0 + (lane >> 2);
        elp[wn][rr] = pel0; elp[wn][rr + 8] = pel8;
        erp[wn][rr] = per0; erp[wn][rr + 8] = per8;
    }
    __syncthreads();
    if (tid < 128) {
        int row = row0 + tid;
        if (row < NN) {
            g_el2[row] = elp[0][tid] + elp[1][tid];
            g_er2[row] = erp[0][tid] + erp[1][tid];
        }
    }
}

// ---------------- CSR row pointers from sorted dst ----------------
__global__ void rowptr_kernel(const int* __restrict__ dst)
{
    int n = blockIdx.x * blockDim.x + threadIdx.x;
    if (n > NN) return;
    int lo = 0, hi = NE;
    while (lo < hi) {
        int mid = (lo + hi) >> 1;
        if (dst[mid] < n) lo = mid + 1; else hi = mid;
    }
    g_rowptr[n] = lo;
}

// ---------------- layer-1 segment softmax + aggregation: WARP per dst node ----------------
// Softmax shift dropped (shift-invariant; logits ~N(0,1.1), no overflow possible).
__global__ void agg1_kernel(const int* __restrict__ src, const float* __restrict__ b1)
{
    __shared__ float4 smw[8][32];
    __shared__ int    smsrc[8][32];

    const int w    = threadIdx.x >> 5;
    const int lane = threadIdx.x & 31;
    const int n    = blockIdx.x * 8 + w;
    const int s = g_rowptr[n];
    const int e = g_rowptr[n + 1];
    const float4 er = *reinterpret_cast<const float4*>(g_er1 + n * 4);

    const int h = lane >> 3;
    float acc[8] = {0.f, 0.f, 0.f, 0.f, 0.f, 0.f, 0.f, 0.f};
    float den = 0.f;

    for (int base = s; base < e; base += 32) {
        int cnt = min(32, e - base);
        if (lane < cnt) {
            int sj = src[base + lane];
            float4 el = *reinterpret_cast<const float4*>(g_el1 + sj * 4);
            float4 wv; float v;
            v = el.x + er.x; v = v > 0.f ? v : 0.2f * v; wv.x = __expf(v);
            v = el.y + er.y; v = v > 0.f ? v : 0.2f * v; wv.y = __expf(v);
            v = el.z + er.z; v = v > 0.f ? v : 0.2f * v; wv.z = __expf(v);
            v = el.w + er.w; v = v > 0.f ? v : 0.2f * v; wv.w = __expf(v);
            smw[w][lane]   = wv;
            smsrc[w][lane] = sj;
        }
        __syncwarp();
#pragma unroll 2
        for (int jj = 0; jj < cnt; ++jj) {
            float wt = reinterpret_cast<const float*>(&smw[w][jj])[h];
            int  sj  = smsrc[w][jj];
            den += wt;
            const float4* fr = reinterpret_cast<const float4*>(g_fs1 + (size_t)sj * 256) + lane * 2;
            float4 f0 = fr[0], f1 = fr[1];
            acc[0] = fmaf(wt, f0.x, acc[0]); acc[1] = fmaf(wt, f0.y, acc[1]);
            acc[2] = fmaf(wt, f0.z, acc[2]); acc[3] = fmaf(wt, f0.w, acc[3]);
            acc[4] = fmaf(wt, f1.x, acc[4]); acc[5] = fmaf(wt, f1.y, acc[5]);
            acc[6] = fmaf(wt, f1.z, acc[6]); acc[7] = fmaf(wt, f1.w, acc[7]);
        }
        __syncwarp();
    }

    float rden = (e > s) ? 1.f / den : 0.f;
    float4 bb0 = *reinterpret_cast<const float4*>(b1 + lane * 8);
    float4 bb1 = *reinterpret_cast<const float4*>(b1 + lane * 8 + 4);
    float4 o0, o1;
    o0.x = fmaxf(acc[0] * rden + bb0.x, 0.f); o0.y = fmaxf(acc[1] * rden + bb0.y, 0.f);
    o0.z = fmaxf(acc[2] * rden + bb0.z, 0.f); o0.w = fmaxf(acc[3] * rden + bb0.w, 0.f);
    o1.x = fmaxf(acc[4] * rden + bb1.x, 0.f); o1.y = fmaxf(acc[5] * rden + bb1.y, 0.f);
    o1.z = fmaxf(acc[6] * rden + bb1.z, 0.f); o1.w = fmaxf(acc[7] * rden + bb1.w, 0.f);
    float* drow = g_h2 + (size_t)n * 256 + lane * 8;
    *reinterpret_cast<float4*>(drow)     = o0;
    *reinterpret_cast<float4*>(drow + 4) = o1;
}

// ---------------- layer-2 segment softmax + aggregation: WARP per dst node ----------------
__global__ void agg2_kernel(const int* __restrict__ src, const float* __restrict__ b2,
                            float* __restrict__ out)
{
    const int w    = threadIdx.x >> 5;
    const int lane = threadIdx.x & 31;
    const int n    = blockIdx.x * 8 + w;
    const int s = g_rowptr[n];
    const int e = g_rowptr[n + 1];
    const float ern = g_er2[n];

    float acc0 = 0.f, acc1 = 0.f, den = 0.f;
    for (int base = s; base < e; base += 32) {
        int cnt = min(32, e - base);
        float wv = 0.f; int sjv = 0;
        if (lane < cnt) {
            sjv = src[base + lane];
            float v = g_el2[sjv] + ern;
            v = v > 0.f ? v : 0.2f * v;
            wv = __expf(v);
        }
#pragma unroll 2
        for (int jj = 0; jj < cnt; ++jj) {
            float wt = __shfl_sync(0xffffffffu, wv, jj);
            int  sj  = __shfl_sync(0xffffffffu, sjv, jj);
            den += wt;
            const float* fr = g_fs2 + (size_t)sj * C2;
            acc0 = fmaf(wt, fr[lane], acc0);
            if (lane < C2 - 32) acc1 = fmaf(wt, fr[lane + 32], acc1);
        }
    }

    float rden = (e > s) ? 1.f / den : 0.f;
    float* orow = out + (size_t)n * C2;
    orow[lane] = acc0 * rden + b2[lane];
    if (lane < C2 - 32) orow[lane + 32] = acc1 * rden + b2[lane + 32];
}

// ---------------- launch ----------------
extern "C" void kernel_launch(void* const* d_in, const int* in_sizes, int n_in,
                              void* d_out, int out_size)
{
    const float* x   = (const float*)d_in[0];
    const float* W1  = (const float*)d_in[1];
    const float* al1 = (const float*)d_in[2];
    const float* ar1 = (const float*)d_in[3];
    const float* b1  = (const float*)d_in[4];
    const float* W2  = (const float*)d_in[5];
    const float* al2 = (const float*)d_in[6];
    const float* ar2 = (const float*)d_in[7];
    const float* b2  = (const float*)d_in[8];
    const int*   src = (const int*)d_in[9];
    const int*   dst = (const int*)d_in[10];
    float* out = (float*)d_out;

    (void)in_sizes; (void)n_in; (void)out_size;

    cudaFuncSetAttribute(gemm1_mma_kernel,
                         cudaFuncAttributeMaxDynamicSharedMemorySize, GEMM_SMEM);
    cudaFuncSetAttribute(gemm2_mma_kernel,
                         cudaFuncAttributeMaxDynamicSharedMemorySize, GEMM_SMEM);

    rowptr_kernel<<<(NN + 1 + 255) / 256, 256>>>(dst);
    wsplit_kernel<<<(65536 + 16384 + 255) / 256, 256>>>(W1, W2);

    // Layer 1: fused GEMM + attention logits, then aggregation
    gemm1_mma_kernel<<<NN_PAD / 128, 512, GEMM_SMEM>>>(x, al1, ar1);
    agg1_kernel<<<NN / 8, 256>>>(src, b1);

    // Layer 2
    gemm2_mma_kernel<<<NN_PAD / 128, 512, GEMM_SMEM>>>(al2, ar2);
    agg2_kernel<<<NN / 8, 256>>>(src, b2, out);
}

// round 6
// speedup vs baseline: 2.7425x; 1.1293x over previous
#include <cuda_runtime.h>
#include <cuda_bf16.h>
#include <cuda_fp16.h>
#include <cstdint>

#define NN  50000
#define NE  800000
#define NN_PAD 50048              // 391 * 128
#define FIN 256
#define H1  4
#define D1  64
#define C2  47

// ---------------- scratch (device globals; no allocation allowed) ----------------
__device__ __align__(16) __half g_fs1[(size_t)NN * FIN];   // layer-1 features, fp16
__device__ __align__(16) float g_h2 [(size_t)NN * FIN];
__device__ __align__(16) float g_el1[NN * H1];
__device__ __align__(16) float g_er1[NN * H1];
__device__ __align__(16) float g_fs2[(size_t)NN * C2];
__device__ __align__(16) float g_el2[NN];
__device__ __align__(16) float g_er2[NN];
__device__ __align__(16) int   g_rowptr[NN + 1];
// bf16 hi/lo splits of W1^T [256,256] and W2^T padded [64,256]
__device__ __align__(16) __nv_bfloat16 g_w1hi[256 * 256];
__device__ __align__(16) __nv_bfloat16 g_w1lo[256 * 256];
__device__ __align__(16) __nv_bfloat16 g_w2hi[64 * 256];
__device__ __align__(16) __nv_bfloat16 g_w2lo[64 * 256];

// ================= warp-level MMA helpers (arch-agnostic PTX, sm_80+) =================
__device__ __forceinline__ uint32_t smem_to_u32(const void* p) {
    uint32_t a;
    asm("{ .reg .u64 t; cvta.to.shared.u64 t, %1; cvt.u32.u64 %0, t; }" : "=r"(a) : "l"(p));
    return a;
}
__device__ __forceinline__ void ldsm_x4(uint32_t addr, uint32_t r[4]) {
    asm volatile("ldmatrix.sync.aligned.m8n8.x4.shared.b16 {%0,%1,%2,%3}, [%4];"
                 : "=r"(r[0]), "=r"(r[1]), "=r"(r[2]), "=r"(r[3]) : "r"(addr));
}
__device__ __forceinline__ void ldsm_x2(uint32_t addr, uint32_t r[2]) {
    asm volatile("ldmatrix.sync.aligned.m8n8.x2.shared.b16 {%0,%1}, [%2];"
                 : "=r"(r[0]), "=r"(r[1]) : "r"(addr));
}
__device__ __forceinline__ void mma_bf16(float c[4], const uint32_t a[4], const uint32_t b[2]) {
    asm volatile("mma.sync.aligned.m16n8k16.row.col.f32.bf16.bf16.f32 "
                 "{%0,%1,%2,%3}, {%4,%5,%6,%7}, {%8,%9}, {%0,%1,%2,%3};"
                 : "+f"(c[0]), "+f"(c[1]), "+f"(c[2]), "+f"(c[3])
                 : "r"(a[0]), "r"(a[1]), "r"(a[2]), "r"(a[3]), "r"(b[0]), "r"(b[1]));
}
__device__ __forceinline__ uint32_t pack_bf16(__nv_bfloat16 a, __nv_bfloat16 b) {
    uint32_t lo = *reinterpret_cast<unsigned short*>(&a);
    uint32_t hi = *reinterpret_cast<unsigned short*>(&b);
    return lo | (hi << 16);
}

// W1[k,n] -> g_w1{hi,lo}[n,k]; W2[k,n] -> g_w2{hi,lo}[n,k] zero-padded to 64 rows.
__global__ void wsplit_kernel(const float* __restrict__ W1, const float* __restrict__ W2)
{
    int idx = blockIdx.x * blockDim.x + threadIdx.x;
    if (idx < 65536) {
        int n = idx & 255, k = idx >> 8;
        float f = W1[(size_t)k * 256 + n];
        __nv_bfloat16 h = __float2bfloat16(f);
        __nv_bfloat16 l = __float2bfloat16(f - __bfloat162float(h));
        g_w1hi[(size_t)n * 256 + k] = h;
        g_w1lo[(size_t)n * 256 + k] = l;
    } else if (idx < 65536 + 16384) {
        int j = idx - 65536;
        int n = j >> 8, k = j & 255;
        float f = (n < C2) ? W2[(size_t)k * C2 + n] : 0.f;
        __nv_bfloat16 h = __float2bfloat16(f);
        __nv_bfloat16 l = __float2bfloat16(f - __bfloat162float(h));
        g_w2hi[(size_t)n * 256 + k] = h;
        g_w2lo[(size_t)n * 256 + k] = l;
    }
}

// ================= fused GEMM + attention-logit kernels =================
#define LDT 264                       // padded row stride in bf16 elems (528 B)
#define OFF_AHI 0
#define OFF_ALO (128 * LDT * 2)
#define OFF_BHI (OFF_ALO + 128 * LDT * 2)
#define OFF_BLO (OFF_BHI + 64 * LDT * 2)
#define GEMM_SMEM (OFF_BLO + 64 * LDT * 2)   // 202752 B dynamic

// ---- load 128 fp32 rows of src (stride 256) into Ah/Al hi/lo smem tiles ----
__device__ __forceinline__ void load_A_split(const float* __restrict__ src, int row0,
                                             __nv_bfloat16* Ah, __nv_bfloat16* Al, int tid)
{
#pragma unroll
    for (int i = 0; i < 16; ++i) {
        int idx = tid + i * 512;              // 0..8191 = 128 rows x 64 float4
        int r = idx >> 6, q = (idx & 63) * 4;
        int gr = row0 + r;
        float4 v = make_float4(0.f, 0.f, 0.f, 0.f);
        if (gr < NN) v = *reinterpret_cast<const float4*>(src + (size_t)gr * 256 + q);
        __nv_bfloat16 hx = __float2bfloat16(v.x), hy = __float2bfloat16(v.y);
        __nv_bfloat16 hz = __float2bfloat16(v.z), hw = __float2bfloat16(v.w);
        __nv_bfloat16 lx = __float2bfloat16(v.x - __bfloat162float(hx));
        __nv_bfloat16 ly = __float2bfloat16(v.y - __bfloat162float(hy));
        __nv_bfloat16 lz = __float2bfloat16(v.z - __bfloat162float(hz));
        __nv_bfloat16 lw = __float2bfloat16(v.w - __bfloat162float(hw));
        *reinterpret_cast<uint2*>(Ah + r * LDT + q) = make_uint2(pack_bf16(hx, hy), pack_bf16(hz, hw));
        *reinterpret_cast<uint2*>(Al + r * LDT + q) = make_uint2(pack_bf16(lx, ly), pack_bf16(lz, lw));
    }
}

// ---- load 64 bf16 rows (stride 256) into B smem tile ----
__device__ __forceinline__ void load_B(const __nv_bfloat16* __restrict__ srcH,
                                       const __nv_bfloat16* __restrict__ srcL,
                                       int rowoff, __nv_bfloat16* Bh, __nv_bfloat16* Bl, int tid)
{
#pragma unroll
    for (int i = 0; i < 4; ++i) {
        int idx = tid + i * 512;              // 0..2047 = 64 rows x 32 uint4
        int r = idx >> 5, c8 = (idx & 31) * 8;
        size_t go = (size_t)(rowoff + r) * 256 + c8;
        *reinterpret_cast<uint4*>(Bh + r * LDT + c8) = *reinterpret_cast<const uint4*>(srcH + go);
        *reinterpret_cast<uint4*>(Bl + r * LDT + c8) = *reinterpret_cast<const uint4*>(srcL + go);
    }
}

// ---- warp MMA over K=256, 3-term bf16 split; returns c[4][4] ----
__device__ __forceinline__ void mma_k256(uint32_t sb, int m0, int n0, float c[4][4])
{
#pragma unroll
    for (int g = 0; g < 4; ++g)
#pragma unroll
        for (int q = 0; q < 4; ++q) c[g][q] = 0.f;

    const int lane = threadIdx.x & 31;
    uint32_t aAh = sb + OFF_AHI + (uint32_t)((m0 + (lane & 15)) * LDT + ((lane >> 4) & 1) * 8) * 2;
    uint32_t aAl = aAh + (OFF_ALO - OFF_AHI);
    uint32_t aBh = sb + OFF_BHI + (uint32_t)((n0 + (lane & 7)) * LDT + ((lane >> 3) & 1) * 8) * 2;
    uint32_t aBl = aBh + (OFF_BLO - OFF_BHI);

#pragma unroll
    for (int ks = 0; ks < 16; ++ks) {
        uint32_t fAh[4], fAl[4];
        ldsm_x4(aAh, fAh);
        ldsm_x4(aAl, fAl);
#pragma unroll
        for (int g = 0; g < 4; ++g) {
            uint32_t bh[2], bl[2];
            ldsm_x2(aBh + g * 8 * LDT * 2, bh);
            ldsm_x2(aBl + g * 8 * LDT * 2, bl);
            mma_bf16(c[g], fAh, bh);
            mma_bf16(c[g], fAl, bh);
            mma_bf16(c[g], fAh, bl);
        }
        aAh += 32; aAl += 32; aBh += 32; aBl += 32;
    }
}

// ================= GEMM1 (x @ W1) + el1/er1, 4 head-tiles per CTA; fs1 stored fp16 =========
__global__ void __launch_bounds__(512, 1) gemm1_mma_kernel(const float* __restrict__ x,
                                                           const float* __restrict__ al1,
                                                           const float* __restrict__ ar1)
{
    extern __shared__ __align__(16) char dsm[];
    __shared__ float als[256], ars[256];
    __shared__ float elp[2][128], erp[2][128];

    const uint32_t sb = smem_to_u32(dsm);
    const int tid  = threadIdx.x;
    const int lane = tid & 31;
    const int wid  = tid >> 5;
    const int wm = wid >> 1, wn = wid & 1;
    const int m0 = wm * 16, n0 = wn * 32;
    const int row0 = blockIdx.x * 128;

    __nv_bfloat16* Ah = reinterpret_cast<__nv_bfloat16*>(dsm + OFF_AHI);
    __nv_bfloat16* Al = reinterpret_cast<__nv_bfloat16*>(dsm + OFF_ALO);
    __nv_bfloat16* Bh = reinterpret_cast<__nv_bfloat16*>(dsm + OFF_BHI);
    __nv_bfloat16* Bl = reinterpret_cast<__nv_bfloat16*>(dsm + OFF_BLO);

    load_A_split(x, row0, Ah, Al, tid);
    if (tid < 256) { als[tid] = al1[tid]; ars[tid] = ar1[tid]; }

#pragma unroll 1
    for (int ct = 0; ct < 4; ++ct) {
        const int col0 = ct * 64;
        load_B(g_w1hi, g_w1lo, col0, Bh, Bl, tid);
        __syncthreads();

        float c[4][4];
        mma_k256(sb, m0, n0, c);

        // ---- store C (fp16) + per-row attention partials for head ct ----
        const int r0 = row0 + m0 + (lane >> 2);
        const int cbl = n0 + 2 * (lane & 3);         // col within head tile
        float pel0 = 0.f, per0 = 0.f, pel8 = 0.f, per8 = 0.f;
#pragma unroll
        for (int g = 0; g < 4; ++g) {
            float a0 = als[col0 + cbl + g * 8], a1 = als[col0 + cbl + g * 8 + 1];
            float b0 = ars[col0 + cbl + g * 8], b1 = ars[col0 + cbl + g * 8 + 1];
            pel0 += c[g][0] * a0 + c[g][1] * a1;
            per0 += c[g][0] * b0 + c[g][1] * b1;
            pel8 += c[g][2] * a0 + c[g][3] * a1;
            per8 += c[g][2] * b0 + c[g][3] * b1;
            if (r0 < NN)
                *reinterpret_cast<__half2*>(g_fs1 + (size_t)r0 * 256 + col0 + cbl + g * 8) =
                    __floats2half2_rn(c[g][0], c[g][1]);
            if (r0 + 8 < NN)
                *reinterpret_cast<__half2*>(g_fs1 + (size_t)(r0 + 8) * 256 + col0 + cbl + g * 8) =
                    __floats2half2_rn(c[g][2], c[g][3]);
        }
        pel0 += __shfl_xor_sync(0xffffffffu, pel0, 1); pel0 += __shfl_xor_sync(0xffffffffu, pel0, 2);
        per0 += __shfl_xor_sync(0xffffffffu, per0, 1); per0 += __shfl_xor_sync(0xffffffffu, per0, 2);
        pel8 += __shfl_xor_sync(0xffffffffu, pel8, 1); pel8 += __shfl_xor_sync(0xffffffffu, pel8, 2);
        per8 += __shfl_xor_sync(0xffffffffu, per8, 1); per8 += __shfl_xor_sync(0xffffffffu, per8, 2);
        if ((lane & 3) == 0) {
            int rr = m0 + (lane >> 2);
            elp[wn][rr] = pel0; elp[wn][rr + 8] = pel8;
            erp[wn][rr] = per0; erp[wn][rr + 8] = per8;
        }
        __syncthreads();
        if (tid < 128) {
            int row = row0 + tid;
            if (row < NN) {
                g_el1[row * 4 + ct] = elp[0][tid] + elp[1][tid];
                g_er1[row * 4 + ct] = erp[0][tid] + erp[1][tid];
            }
        }
    }
}

// ================= GEMM2 (h2 @ W2) + el2/er2 =================
__global__ void __launch_bounds__(512, 1) gemm2_mma_kernel(const float* __restrict__ al2,
                                                           const float* __restrict__ ar2)
{
    extern __shared__ __align__(16) char dsm[];
    __shared__ float als[64], ars[64];
    __shared__ float elp[2][128], erp[2][128];

    const uint32_t sb = smem_to_u32(dsm);
    const int tid  = threadIdx.x;
    const int lane = tid & 31;
    const int wid  = tid >> 5;
    const int wm = wid >> 1, wn = wid & 1;
    const int m0 = wm * 16, n0 = wn * 32;
    const int row0 = blockIdx.x * 128;

    __nv_bfloat16* Ah = reinterpret_cast<__nv_bfloat16*>(dsm + OFF_AHI);
    __nv_bfloat16* Al = reinterpret_cast<__nv_bfloat16*>(dsm + OFF_ALO);
    __nv_bfloat16* Bh = reinterpret_cast<__nv_bfloat16*>(dsm + OFF_BHI);
    __nv_bfloat16* Bl = reinterpret_cast<__nv_bfloat16*>(dsm + OFF_BLO);

    load_A_split(g_h2, row0, Ah, Al, tid);
    if (tid < 64) {
        als[tid] = (tid < C2) ? al2[tid] : 0.f;
        ars[tid] = (tid < C2) ? ar2[tid] : 0.f;
    }
    load_B(g_w2hi, g_w2lo, 0, Bh, Bl, tid);
    __syncthreads();

    float c[4][4];
    mma_k256(sb, m0, n0, c);

    const int r0 = row0 + m0 + (lane >> 2);
    const int cbl = n0 + 2 * (lane & 3);
    float pel0 = 0.f, per0 = 0.f, pel8 = 0.f, per8 = 0.f;
#pragma unroll
    for (int g = 0; g < 4; ++g) {
        int cc = cbl + g * 8;
        float a0 = als[cc], a1 = als[cc + 1];
        float b0 = ars[cc], b1 = ars[cc + 1];
        pel0 += c[g][0] * a0 + c[g][1] * a1;
        per0 += c[g][0] * b0 + c[g][1] * b1;
        pel8 += c[g][2] * a0 + c[g][3] * a1;
        per8 += c[g][2] * b0 + c[g][3] * b1;
        if (r0 < NN) {
            if (cc < C2)     g_fs2[(size_t)r0 * C2 + cc]     = c[g][0];
            if (cc + 1 < C2) g_fs2[(size_t)r0 * C2 + cc + 1] = c[g][1];
        }
        if (r0 + 8 < NN) {
            if (cc < C2)     g_fs2[(size_t)(r0 + 8) * C2 + cc]     = c[g][2];
            if (cc + 1 < C2) g_fs2[(size_t)(r0 + 8) * C2 + cc + 1] = c[g][3];
        }
    }
    pel0 += __shfl_xor_sync(0xffffffffu, pel0, 1); pel0 += __shfl_xor_sync(0xffffffffu, pel0, 2);
    per0 += __shfl_xor_sync(0xffffffffu, per0, 1); per0 += __shfl_xor_sync(0xffffffffu, per0, 2);
    pel8 += __shfl_xor_sync(0xffffffffu, pel8, 1); pel8 += __shfl_xor_sync(0xffffffffu, pel8, 2);
    per8 += __shfl_xor_sync(0xffffffffu, per8, 1); per8 += __shfl_xor_sync(0xffffffffu, per8, 2);
    if ((lane & 3) == 0) {
        int rr = m0 + (lane >> 2);
        elp[wn][rr] = pel0; elp[wn][rr + 8] = pel8;
        erp[wn][rr] = per0; erp[wn][rr + 8] = per8;
    }
    __syncthreads();
    if (tid < 128) {
        int row = row0 + tid;
        if (row < NN) {
            g_el2[row] = elp[0][tid] + elp[1][tid];
            g_er2[row] = erp[0][tid] + erp[1][tid];
        }
    }
}

// ---------------- CSR row pointers from sorted dst ----------------
__global__ void rowptr_kernel(const int* __restrict__ dst)
{
    int n = blockIdx.x * blockDim.x + threadIdx.x;
    if (n > NN) return;
    int lo = 0, hi = NE;
    while (lo < hi) {
        int mid = (lo + hi) >> 1;
        if (dst[mid] < n) lo = mid + 1; else hi = mid;
    }
    g_rowptr[n] = lo;
}

// ---------------- layer-1 segment softmax + aggregation: WARP per dst node, fp16 gather ----
__global__ void agg1_kernel(const int* __restrict__ src, const float* __restrict__ b1)
{
    __shared__ float4 smw[8][32];
    __shared__ int    smsrc[8][32];

    const int w    = threadIdx.x >> 5;
    const int lane = threadIdx.x & 31;
    const int n    = blockIdx.x * 8 + w;
    const int s = g_rowptr[n];
    const int e = g_rowptr[n + 1];
    const float4 er = *reinterpret_cast<const float4*>(g_er1 + n * 4);

    const int h = lane >> 3;
    float acc[8] = {0.f, 0.f, 0.f, 0.f, 0.f, 0.f, 0.f, 0.f};
    float den = 0.f;

    for (int base = s; base < e; base += 32) {
        int cnt = min(32, e - base);
        if (lane < cnt) {
            int sj = src[base + lane];
            float4 el = *reinterpret_cast<const float4*>(g_el1 + sj * 4);
            float4 wv; float v;
            v = el.x + er.x; v = v > 0.f ? v : 0.2f * v; wv.x = __expf(v);
            v = el.y + er.y; v = v > 0.f ? v : 0.2f * v; wv.y = __expf(v);
            v = el.z + er.z; v = v > 0.f ? v : 0.2f * v; wv.z = __expf(v);
            v = el.w + er.w; v = v > 0.f ? v : 0.2f * v; wv.w = __expf(v);
            smw[w][lane]   = wv;
            smsrc[w][lane] = sj;
        }
        __syncwarp();
#pragma unroll 4
        for (int jj = 0; jj < cnt; ++jj) {
            float wt = reinterpret_cast<const float*>(&smw[w][jj])[h];
            int  sj  = smsrc[w][jj];
            den += wt;
            // one LDG.128: this lane's 8 fp16 features
            uint4 f = *reinterpret_cast<const uint4*>(g_fs1 + (size_t)sj * 256 + lane * 8);
            const __half2* hp = reinterpret_cast<const __half2*>(&f);
            float2 f0 = __half22float2(hp[0]);
            float2 f1 = __half22float2(hp[1]);
            float2 f2 = __half22float2(hp[2]);
            float2 f3 = __half22float2(hp[3]);
            acc[0] = fmaf(wt, f0.x, acc[0]); acc[1] = fmaf(wt, f0.y, acc[1]);
            acc[2] = fmaf(wt, f1.x, acc[2]); acc[3] = fmaf(wt, f1.y, acc[3]);
            acc[4] = fmaf(wt, f2.x, acc[4]); acc[5] = fmaf(wt, f2.y, acc[5]);
            acc[6] = fmaf(wt, f3.x, acc[6]); acc[7] = fmaf(wt, f3.y, acc[7]);
        }
        __syncwarp();
    }

    float rden = (e > s) ? 1.f / den : 0.f;
    float4 bb0 = *reinterpret_cast<const float4*>(b1 + lane * 8);
    float4 bb1 = *reinterpret_cast<const float4*>(b1 + lane * 8 + 4);
    float4 o0, o1;
    o0.x = fmaxf(acc[0] * rden + bb0.x, 0.f); o0.y = fmaxf(acc[1] * rden + bb0.y, 0.f);
    o0.z = fmaxf(acc[2] * rden + bb0.z, 0.f); o0.w = fmaxf(acc[3] * rden + bb0.w, 0.f);
    o1.x = fmaxf(acc[4] * rden + bb1.x, 0.f); o1.y = fmaxf(acc[5] * rden + bb1.y, 0.f);
    o1.z = fmaxf(acc[6] * rden + bb1.z, 0.f); o1.w = fmaxf(acc[7] * rden + bb1.w, 0.f);
    float* drow = g_h2 + (size_t)n * 256 + lane * 8;
    *reinterpret_cast<float4*>(drow)     = o0;
    *reinterpret_cast<float4*>(drow + 4) = o1;
}

// ---------------- layer-2 segment softmax + aggregation: WARP per dst node ----------------
__global__ void agg2_kernel(const int* __restrict__ src, const float* __restrict__ b2,
                            float* __restrict__ out)
{
    const int w    = threadIdx.x >> 5;
    const int lane = threadIdx.x & 31;
    const int n    = blockIdx.x * 8 + w;
    const int s = g_rowptr[n];
    const int e = g_rowptr[n + 1];
    const float ern = g_er2[n];

    float acc0 = 0.f, acc1 = 0.f, den = 0.f;
    for (int base = s; base < e; base += 32) {
        int cnt = min(32, e - base);
        float wv = 0.f; int sjv = 0;
        if (lane < cnt) {
            sjv = src[base + lane];
            float v = g_el2[sjv] + ern;
            v = v > 0.f ? v : 0.2f * v;
            wv = __expf(v);
        }
#pragma unroll 4
        for (int jj = 0; jj < cnt; ++jj) {
            float wt = __shfl_sync(0xffffffffu, wv, jj);
            int  sj  = __shfl_sync(0xffffffffu, sjv, jj);
            den += wt;
            const float* fr = g_fs2 + (size_t)sj * C2;
            acc0 = fmaf(wt, fr[lane], acc0);
            if (lane < C2 - 32) acc1 = fmaf(wt, fr[lane + 32], acc1);
        }
    }

    float rden = (e > s) ? 1.f / den : 0.f;
    float* orow = out + (size_t)n * C2;
    orow[lane] = acc0 * rden + b2[lane];
    if (lane < C2 - 32) orow[lane + 32] = acc1 * rden + b2[lane + 32];
}

// ---------------- launch ----------------
extern "C" void kernel_launch(void* const* d_in, const int* in_sizes, int n_in,
                              void* d_out, int out_size)
{
    const float* x   = (const float*)d_in[0];
    const float* W1  = (const float*)d_in[1];
    const float* al1 = (const float*)d_in[2];
    const float* ar1 = (const float*)d_in[3];
    const float* b1  = (const float*)d_in[4];
    const float* W2  = (const float*)d_in[5];
    const float* al2 = (const float*)d_in[6];
    const float* ar2 = (const float*)d_in[7];
    const float* b2  = (const float*)d_in[8];
    const int*   src = (const int*)d_in[9];
    const int*   dst = (const int*)d_in[10];
    float* out = (float*)d_out;

    (void)in_sizes; (void)n_in; (void)out_size;

    cudaFuncSetAttribute(gemm1_mma_kernel,
                         cudaFuncAttributeMaxDynamicSharedMemorySize, GEMM_SMEM);
    cudaFuncSetAttribute(gemm2_mma_kernel,
                         cudaFuncAttributeMaxDynamicSharedMemorySize, GEMM_SMEM);

    rowptr_kernel<<<(NN + 1 + 255) / 256, 256>>>(dst);
    wsplit_kernel<<<(65536 + 16384 + 255) / 256, 256>>>(W1, W2);

    // Layer 1: fused GEMM + attention logits, then aggregation
    gemm1_mma_kernel<<<NN_PAD / 128, 512, GEMM_SMEM>>>(x, al1, ar1);
    agg1_kernel<<<NN / 8, 256>>>(src, b1);

    // Layer 2
    gemm2_mma_kernel<<<NN_PAD / 128, 512, GEMM_SMEM>>>(al2, ar2);
    agg2_kernel<<<NN / 8, 256>>>(src, b2, out);
}

// round 7
// speedup vs baseline: 3.1820x; 1.1603x over previous
#include <cuda_runtime.h>
#include <cuda_bf16.h>
#include <cuda_fp16.h>
#include <cstdint>

#define NN  50000
#define NE  800000
#define NN_PAD 50048              // 391 * 128
#define FIN 256
#define H1  4
#define D1  64
#define C2  47

// ---------------- scratch (device globals; no allocation allowed) ----------------
__device__ __align__(16) __half g_fs1[(size_t)NN * FIN];   // layer-1 features, fp16
__device__ __align__(16) __half g_h2 [(size_t)NN * FIN];   // relu(layer-1 out), fp16
__device__ __align__(16) __half g_fs2h[(size_t)NN * 64];   // layer-2 features, fp16 padded
__device__ __align__(16) float g_el1[NN * H1];
__device__ __align__(16) float g_er1[NN * H1];
__device__ __align__(16) float g_el2[NN];
__device__ __align__(16) float g_er2[NN];
__device__ __align__(16) int   g_rowptr[NN + 1];
// bf16 hi/lo split of W1^T [256,256]; fp16 hi/lo split of W2^T padded [64,256]
__device__ __align__(16) __nv_bfloat16 g_w1hi[256 * 256];
__device__ __align__(16) __nv_bfloat16 g_w1lo[256 * 256];
__device__ __align__(16) __half g_w2hi[64 * 256];
__device__ __align__(16) __half g_w2lo[64 * 256];

// ================= warp-level MMA helpers (arch-agnostic PTX, sm_80+) =================
__device__ __forceinline__ uint32_t smem_to_u32(const void* p) {
    uint32_t a;
    asm("{ .reg .u64 t; cvta.to.shared.u64 t, %1; cvt.u32.u64 %0, t; }" : "=r"(a) : "l"(p));
    return a;
}
__device__ __forceinline__ void ldsm_x4(uint32_t addr, uint32_t r[4]) {
    asm volatile("ldmatrix.sync.aligned.m8n8.x4.shared.b16 {%0,%1,%2,%3}, [%4];"
                 : "=r"(r[0]), "=r"(r[1]), "=r"(r[2]), "=r"(r[3]) : "r"(addr));
}
__device__ __forceinline__ void ldsm_x2(uint32_t addr, uint32_t r[2]) {
    asm volatile("ldmatrix.sync.aligned.m8n8.x2.shared.b16 {%0,%1}, [%2];"
                 : "=r"(r[0]), "=r"(r[1]) : "r"(addr));
}
__device__ __forceinline__ void mma_bf16(float c[4], const uint32_t a[4], const uint32_t b[2]) {
    asm volatile("mma.sync.aligned.m16n8k16.row.col.f32.bf16.bf16.f32 "
                 "{%0,%1,%2,%3}, {%4,%5,%6,%7}, {%8,%9}, {%0,%1,%2,%3};"
                 : "+f"(c[0]), "+f"(c[1]), "+f"(c[2]), "+f"(c[3])
                 : "r"(a[0]), "r"(a[1]), "r"(a[2]), "r"(a[3]), "r"(b[0]), "r"(b[1]));
}
__device__ __forceinline__ void mma_f16(float c[4], const uint32_t a[4], const uint32_t b[2]) {
    asm volatile("mma.sync.aligned.m16n8k16.row.col.f32.f16.f16.f32 "
                 "{%0,%1,%2,%3}, {%4,%5,%6,%7}, {%8,%9}, {%0,%1,%2,%3};"
                 : "+f"(c[0]), "+f"(c[1]), "+f"(c[2]), "+f"(c[3])
                 : "r"(a[0]), "r"(a[1]), "r"(a[2]), "r"(a[3]), "r"(b[0]), "r"(b[1]));
}
__device__ __forceinline__ uint32_t pack_bf16(__nv_bfloat16 a, __nv_bfloat16 b) {
    uint32_t lo = *reinterpret_cast<unsigned short*>(&a);
    uint32_t hi = *reinterpret_cast<unsigned short*>(&b);
    return lo | (hi << 16);
}
__device__ __forceinline__ void fma_x2(float2& d, const float2& a, const float2& b)
{
    asm("fma.rn.f32x2 %0, %1, %2, %0;"
        : "+l"(reinterpret_cast<unsigned long long&>(d))
        : "l"(reinterpret_cast<const unsigned long long&>(a)),
          "l"(reinterpret_cast<const unsigned long long&>(b)));
}

// W1[k,n] -> g_w1{hi,lo}[n,k] (bf16); W2[k,n] -> g_w2{hi,lo}[n,k] (fp16, zero-padded to 64 rows)
__global__ void wsplit_kernel(const float* __restrict__ W1, const float* __restrict__ W2)
{
    int idx = blockIdx.x * blockDim.x + threadIdx.x;
    if (idx < 65536) {
        int n = idx & 255, k = idx >> 8;
        float f = W1[(size_t)k * 256 + n];
        __nv_bfloat16 h = __float2bfloat16(f);
        __nv_bfloat16 l = __float2bfloat16(f - __bfloat162float(h));
        g_w1hi[(size_t)n * 256 + k] = h;
        g_w1lo[(size_t)n * 256 + k] = l;
    } else if (idx < 65536 + 16384) {
        int j = idx - 65536;
        int n = j >> 8, k = j & 255;
        float f = (n < C2) ? W2[(size_t)k * C2 + n] : 0.f;
        __half h = __float2half_rn(f);
        __half l = __float2half_rn(f - __half2float(h));
        g_w2hi[(size_t)n * 256 + k] = h;
        g_w2lo[(size_t)n * 256 + k] = l;
    }
}

// ================= fused GEMM + attention-logit kernels =================
#define LDT 264                       // padded row stride in 16-bit elems (528 B)
#define OFF_AHI 0
#define OFF_ALO (128 * LDT * 2)
#define OFF_BHI (OFF_ALO + 128 * LDT * 2)
#define OFF_BLO (OFF_BHI + 64 * LDT * 2)
#define GEMM_SMEM (OFF_BLO + 64 * LDT * 2)   // 202752 B dynamic (gemm1)
// gemm2 layout: fp16 A single copy + B hi/lo
#define OFF2_A   0
#define OFF2_BHI (128 * LDT * 2)
#define OFF2_BLO (OFF2_BHI + 64 * LDT * 2)
#define GEMM2_SMEM (OFF2_BLO + 64 * LDT * 2)  // 135168 B dynamic

// ---- load 128 fp32 rows of src (stride 256) into hi/lo bf16 smem tiles ----
__device__ __forceinline__ void load_A_split(const float* __restrict__ src, int row0,
                                             __nv_bfloat16* Ah, __nv_bfloat16* Al, int tid)
{
#pragma unroll
    for (int i = 0; i < 16; ++i) {
        int idx = tid + i * 512;              // 0..8191 = 128 rows x 64 float4
        int r = idx >> 6, q = (idx & 63) * 4;
        int gr = row0 + r;
        float4 v = make_float4(0.f, 0.f, 0.f, 0.f);
        if (gr < NN) v = *reinterpret_cast<const float4*>(src + (size_t)gr * 256 + q);
        __nv_bfloat16 hx = __float2bfloat16(v.x), hy = __float2bfloat16(v.y);
        __nv_bfloat16 hz = __float2bfloat16(v.z), hw = __float2bfloat16(v.w);
        __nv_bfloat16 lx = __float2bfloat16(v.x - __bfloat162float(hx));
        __nv_bfloat16 ly = __float2bfloat16(v.y - __bfloat162float(hy));
        __nv_bfloat16 lz = __float2bfloat16(v.z - __bfloat162float(hz));
        __nv_bfloat16 lw = __float2bfloat16(v.w - __bfloat162float(hw));
        *reinterpret_cast<uint2*>(Ah + r * LDT + q) = make_uint2(pack_bf16(hx, hy), pack_bf16(hz, hw));
        *reinterpret_cast<uint2*>(Al + r * LDT + q) = make_uint2(pack_bf16(lx, ly), pack_bf16(lz, lw));
    }
}

// ---- copy 16-bit rows (stride 256) into padded smem tile: NR rows ----
template <int NR>
__device__ __forceinline__ void load_tile16(const __half* __restrict__ srcA, int rowoff, int maxrow,
                                            __half* Dst, int tid)
{
#pragma unroll
    for (int i = 0; i < NR * 32 / 512; ++i) {
        int idx = tid + i * 512;
        int r = idx >> 5, c8 = (idx & 31) * 8;
        int gr = rowoff + r;
        uint4 v = make_uint4(0u, 0u, 0u, 0u);
        if (gr < maxrow) v = *reinterpret_cast<const uint4*>(srcA + (size_t)gr * 256 + c8);
        *reinterpret_cast<uint4*>(Dst + r * LDT + c8) = v;
    }
}
__device__ __forceinline__ void load_B_bf16(const __nv_bfloat16* __restrict__ srcH,
                                            const __nv_bfloat16* __restrict__ srcL,
                                            int rowoff, __nv_bfloat16* Bh, __nv_bfloat16* Bl, int tid)
{
#pragma unroll
    for (int i = 0; i < 4; ++i) {
        int idx = tid + i * 512;              // 64 rows x 32 uint4
        int r = idx >> 5, c8 = (idx & 31) * 8;
        size_t go = (size_t)(rowoff + r) * 256 + c8;
        *reinterpret_cast<uint4*>(Bh + r * LDT + c8) = *reinterpret_cast<const uint4*>(srcH + go);
        *reinterpret_cast<uint4*>(Bl + r * LDT + c8) = *reinterpret_cast<const uint4*>(srcL + go);
    }
}

// ================= GEMM1 (x @ W1) + el1/er1, 4 head-tiles per CTA; fs1 stored fp16 =========
__global__ void __launch_bounds__(512, 1) gemm1_mma_kernel(const float* __restrict__ x,
                                                           const float* __restrict__ al1,
                                                           const float* __restrict__ ar1)
{
    extern __shared__ __align__(16) char dsm[];
    __shared__ float als[256], ars[256];
    __shared__ float elp[2][128], erp[2][128];

    const uint32_t sb = smem_to_u32(dsm);
    const int tid  = threadIdx.x;
    const int lane = tid & 31;
    const int wid  = tid >> 5;
    const int wm = wid >> 1, wn = wid & 1;
    const int m0 = wm * 16, n0 = wn * 32;
    const int row0 = blockIdx.x * 128;

    __nv_bfloat16* Ah = reinterpret_cast<__nv_bfloat16*>(dsm + OFF_AHI);
    __nv_bfloat16* Al = reinterpret_cast<__nv_bfloat16*>(dsm + OFF_ALO);
    __nv_bfloat16* Bh = reinterpret_cast<__nv_bfloat16*>(dsm + OFF_BHI);
    __nv_bfloat16* Bl = reinterpret_cast<__nv_bfloat16*>(dsm + OFF_BLO);

    load_A_split(x, row0, Ah, Al, tid);
    if (tid < 256) { als[tid] = al1[tid]; ars[tid] = ar1[tid]; }

#pragma unroll 1
    for (int ct = 0; ct < 4; ++ct) {
        const int col0 = ct * 64;
        load_B_bf16(g_w1hi, g_w1lo, col0, Bh, Bl, tid);
        __syncthreads();

        float c[4][4];
#pragma unroll
        for (int g = 0; g < 4; ++g)
#pragma unroll
            for (int q = 0; q < 4; ++q) c[g][q] = 0.f;
        {
            uint32_t aAh = sb + OFF_AHI + (uint32_t)((m0 + (lane & 15)) * LDT + ((lane >> 4) & 1) * 8) * 2;
            uint32_t aAl = aAh + (OFF_ALO - OFF_AHI);
            uint32_t aBh = sb + OFF_BHI + (uint32_t)((n0 + (lane & 7)) * LDT + ((lane >> 3) & 1) * 8) * 2;
            uint32_t aBl = aBh + (OFF_BLO - OFF_BHI);
#pragma unroll
            for (int ks = 0; ks < 16; ++ks) {
                uint32_t fAh[4], fAl[4];
                ldsm_x4(aAh, fAh);
                ldsm_x4(aAl, fAl);
#pragma unroll
                for (int g = 0; g < 4; ++g) {
                    uint32_t bh[2], bl[2];
                    ldsm_x2(aBh + g * 8 * LDT * 2, bh);
                    ldsm_x2(aBl + g * 8 * LDT * 2, bl);
                    mma_bf16(c[g], fAh, bh);
                    mma_bf16(c[g], fAl, bh);
                    mma_bf16(c[g], fAh, bl);
                }
                aAh += 32; aAl += 32; aBh += 32; aBl += 32;
            }
        }

        // ---- store C (fp16) + per-row attention partials for head ct ----
        const int r0 = row0 + m0 + (lane >> 2);
        const int cbl = n0 + 2 * (lane & 3);
        float pel0 = 0.f, per0 = 0.f, pel8 = 0.f, per8 = 0.f;
#pragma unroll
        for (int g = 0; g < 4; ++g) {
            float a0 = als[col0 + cbl + g * 8], a1 = als[col0 + cbl + g * 8 + 1];
            float b0 = ars[col0 + cbl + g * 8], b1 = ars[col0 + cbl + g * 8 + 1];
            pel0 += c[g][0] * a0 + c[g][1] * a1;
            per0 += c[g][0] * b0 + c[g][1] * b1;
            pel8 += c[g][2] * a0 + c[g][3] * a1;
            per8 += c[g][2] * b0 + c[g][3] * b1;
            if (r0 < NN)
                *reinterpret_cast<__half2*>(g_fs1 + (size_t)r0 * 256 + col0 + cbl + g * 8) =
                    __floats2half2_rn(c[g][0], c[g][1]);
            if (r0 + 8 < NN)
                *reinterpret_cast<__half2*>(g_fs1 + (size_t)(r0 + 8) * 256 + col0 + cbl + g * 8) =
                    __floats2half2_rn(c[g][2], c[g][3]);
        }
        pel0 += __shfl_xor_sync(0xffffffffu, pel0, 1); pel0 += __shfl_xor_sync(0xffffffffu, pel0, 2);
        per0 += __shfl_xor_sync(0xffffffffu, per0, 1); per0 += __shfl_xor_sync(0xffffffffu, per0, 2);
        pel8 += __shfl_xor_sync(0xffffffffu, pel8, 1); pel8 += __shfl_xor_sync(0xffffffffu, pel8, 2);
        per8 += __shfl_xor_sync(0xffffffffu, per8, 1); per8 += __shfl_xor_sync(0xffffffffu, per8, 2);
        if ((lane & 3) == 0) {
            int rr = m0 + (lane >> 2);
            elp[wn][rr] = pel0; elp[wn][rr + 8] = pel8;
            erp[wn][rr] = per0; erp[wn][rr + 8] = per8;
        }
        __syncthreads();
        if (tid < 128) {
            int row = row0 + tid;
            if (row < NN) {
                g_el1[row * 4 + ct] = elp[0][tid] + elp[1][tid];
                g_er1[row * 4 + ct] = erp[0][tid] + erp[1][tid];
            }
        }
    }
}

// ================= GEMM2 (h2 fp16 @ W2 fp16-split) + el2/er2; fs2 stored fp16 padded =======
__global__ void __launch_bounds__(512, 1) gemm2_mma_kernel(const float* __restrict__ al2,
                                                           const float* __restrict__ ar2)
{
    extern __shared__ __align__(16) char dsm[];
    __shared__ float als[64], ars[64];
    __shared__ float elp[2][128], erp[2][128];

    const uint32_t sb = smem_to_u32(dsm);
    const int tid  = threadIdx.x;
    const int lane = tid & 31;
    const int wid  = tid >> 5;
    const int wm = wid >> 1, wn = wid & 1;
    const int m0 = wm * 16, n0 = wn * 32;
    const int row0 = blockIdx.x * 128;

    __half* Aa = reinterpret_cast<__half*>(dsm + OFF2_A);
    __half* Bh = reinterpret_cast<__half*>(dsm + OFF2_BHI);
    __half* Bl = reinterpret_cast<__half*>(dsm + OFF2_BLO);

    load_tile16<128>(g_h2, row0, NN, Aa, tid);
    if (tid < 64) {
        als[tid] = (tid < C2) ? al2[tid] : 0.f;
        ars[tid] = (tid < C2) ? ar2[tid] : 0.f;
    }
    // B: 64 rows hi + 64 rows lo
#pragma unroll
    for (int i = 0; i < 4; ++i) {
        int idx = tid + i * 512;
        int r = idx >> 5, c8 = (idx & 31) * 8;
        size_t go = (size_t)r * 256 + c8;
        *reinterpret_cast<uint4*>(Bh + r * LDT + c8) = *reinterpret_cast<const uint4*>(g_w2hi + go);
        *reinterpret_cast<uint4*>(Bl + r * LDT + c8) = *reinterpret_cast<const uint4*>(g_w2lo + go);
    }
    __syncthreads();

    float c[4][4];
#pragma unroll
    for (int g = 0; g < 4; ++g)
#pragma unroll
        for (int q = 0; q < 4; ++q) c[g][q] = 0.f;
    {
        uint32_t aA  = sb + OFF2_A + (uint32_t)((m0 + (lane & 15)) * LDT + ((lane >> 4) & 1) * 8) * 2;
        uint32_t aBh = sb + OFF2_BHI + (uint32_t)((n0 + (lane & 7)) * LDT + ((lane >> 3) & 1) * 8) * 2;
        uint32_t aBl = aBh + (OFF2_BLO - OFF2_BHI);
#pragma unroll
        for (int ks = 0; ks < 16; ++ks) {
            uint32_t fA[4];
            ldsm_x4(aA, fA);
#pragma unroll
            for (int g = 0; g < 4; ++g) {
                uint32_t bh[2], bl[2];
                ldsm_x2(aBh + g * 8 * LDT * 2, bh);
                ldsm_x2(aBl + g * 8 * LDT * 2, bl);
                mma_f16(c[g], fA, bh);
                mma_f16(c[g], fA, bl);
            }
            aA += 32; aBh += 32; aBl += 32;
        }
    }

    const int r0 = row0 + m0 + (lane >> 2);
    const int cbl = n0 + 2 * (lane & 3);
    float pel0 = 0.f, per0 = 0.f, pel8 = 0.f, per8 = 0.f;
#pragma unroll
    for (int g = 0; g < 4; ++g) {
        int cc = cbl + g * 8;
        float a0 = als[cc], a1 = als[cc + 1];
        float b0 = ars[cc], b1 = ars[cc + 1];
        pel0 += c[g][0] * a0 + c[g][1] * a1;
        per0 += c[g][0] * b0 + c[g][1] * b1;
        pel8 += c[g][2] * a0 + c[g][3] * a1;
        per8 += c[g][2] * b0 + c[g][3] * b1;
        if (r0 < NN)
            *reinterpret_cast<__half2*>(g_fs2h + (size_t)r0 * 64 + cc) =
                __floats2half2_rn(c[g][0], c[g][1]);
        if (r0 + 8 < NN)
            *reinterpret_cast<__half2*>(g_fs2h + (size_t)(r0 + 8) * 64 + cc) =
                __floats2half2_rn(c[g][2], c[g][3]);
    }
    pel0 += __shfl_xor_sync(0xffffffffu, pel0, 1); pel0 += __shfl_xor_sync(0xffffffffu, pel0, 2);
    per0 += __shfl_xor_sync(0xffffffffu, per0, 1); per0 += __shfl_xor_sync(0xffffffffu, per0, 2);
    pel8 += __shfl_xor_sync(0xffffffffu, pel8, 1); pel8 += __shfl_xor_sync(0xffffffffu, pel8, 2);
    per8 += __shfl_xor_sync(0xffffffffu, per8, 1); per8 += __shfl_xor_sync(0xffffffffu, per8, 2);
    if ((lane & 3) == 0) {
        int rr = m0 + (lane >> 2);
        elp[wn][rr] = pel0; elp[wn][rr + 8] = pel8;
        erp[wn][rr] = per0; erp[wn][rr + 8] = per8;
    }
    __syncthreads();
    if (tid < 128) {
        int row = row0 + tid;
        if (row < NN) {
            g_el2[row] = elp[0][tid] + elp[1][tid];
            g_er2[row] = erp[0][tid] + erp[1][tid];
        }
    }
}

// ---------------- CSR row pointers from sorted dst ----------------
__global__ void rowptr_kernel(const int* __restrict__ dst)
{
    int n = blockIdx.x * blockDim.x + threadIdx.x;
    if (n > NN) return;
    int lo = 0, hi = NE;
    while (lo < hi) {
        int mid = (lo + hi) >> 1;
        if (dst[mid] < n) lo = mid + 1; else hi = mid;
    }
    g_rowptr[n] = lo;
}

// ---------------- layer-1 segment softmax + aggregation: WARP per dst node ----------------
__global__ void __launch_bounds__(256, 6) agg1_kernel(const int* __restrict__ src,
                                                      const float* __restrict__ b1)
{
    __shared__ float4 smw[8][32];
    __shared__ int    smsrc[8][32];

    const int w    = threadIdx.x >> 5;
    const int lane = threadIdx.x & 31;
    const int n    = blockIdx.x * 8 + w;
    const int s = g_rowptr[n];
    const int e = g_rowptr[n + 1];
    const float4 er = *reinterpret_cast<const float4*>(g_er1 + n * 4);

    const int h = lane >> 3;
    float2 acc2[4];
#pragma unroll
    for (int q = 0; q < 4; ++q) acc2[q] = make_float2(0.f, 0.f);
    float den = 0.f;

    for (int base = s; base < e; base += 32) {
        int cnt = min(32, e - base);
        if (lane < cnt) {
            int sj = src[base + lane];
            float4 el = *reinterpret_cast<const float4*>(g_el1 + sj * 4);
            float4 wv; float v;
            v = el.x + er.x; v = v > 0.f ? v : 0.2f * v; wv.x = __expf(v);
            v = el.y + er.y; v = v > 0.f ? v : 0.2f * v; wv.y = __expf(v);
            v = el.z + er.z; v = v > 0.f ? v : 0.2f * v; wv.z = __expf(v);
            v = el.w + er.w; v = v > 0.f ? v : 0.2f * v; wv.w = __expf(v);
            smw[w][lane]   = wv;
            smsrc[w][lane] = sj;
        }
        __syncwarp();
#pragma unroll 4
        for (int jj = 0; jj < cnt; ++jj) {
            float wt = reinterpret_cast<const float*>(&smw[w][jj])[h];
            int  sj  = smsrc[w][jj];
            den += wt;
            float2 w2 = make_float2(wt, wt);
            uint4 f = *reinterpret_cast<const uint4*>(g_fs1 + (size_t)sj * 256 + lane * 8);
            const __half2* hp = reinterpret_cast<const __half2*>(&f);
            fma_x2(acc2[0], __half22float2(hp[0]), w2);
            fma_x2(acc2[1], __half22float2(hp[1]), w2);
            fma_x2(acc2[2], __half22float2(hp[2]), w2);
            fma_x2(acc2[3], __half22float2(hp[3]), w2);
        }
        __syncwarp();
    }

    float rden = (e > s) ? 1.f / den : 0.f;
    float4 bb0 = *reinterpret_cast<const float4*>(b1 + lane * 8);
    float4 bb1 = *reinterpret_cast<const float4*>(b1 + lane * 8 + 4);
    __half2 o[4];
    o[0] = __floats2half2_rn(fmaxf(acc2[0].x * rden + bb0.x, 0.f), fmaxf(acc2[0].y * rden + bb0.y, 0.f));
    o[1] = __floats2half2_rn(fmaxf(acc2[1].x * rden + bb0.z, 0.f), fmaxf(acc2[1].y * rden + bb0.w, 0.f));
    o[2] = __floats2half2_rn(fmaxf(acc2[2].x * rden + bb1.x, 0.f), fmaxf(acc2[2].y * rden + bb1.y, 0.f));
    o[3] = __floats2half2_rn(fmaxf(acc2[3].x * rden + bb1.z, 0.f), fmaxf(acc2[3].y * rden + bb1.w, 0.f));
    *reinterpret_cast<uint4*>(g_h2 + (size_t)n * 256 + lane * 8) = *reinterpret_cast<uint4*>(o);
}

// ---------------- layer-2 segment softmax + aggregation: WARP per dst node, fp16 gather ----
__global__ void __launch_bounds__(256, 6) agg2_kernel(const int* __restrict__ src,
                                                      const float* __restrict__ b2,
                                                      float* __restrict__ out)
{
    const int w    = threadIdx.x >> 5;
    const int lane = threadIdx.x & 31;
    const int n    = blockIdx.x * 8 + w;
    const int s = g_rowptr[n];
    const int e = g_rowptr[n + 1];
    const float ern = g_er2[n];

    float2 acc = make_float2(0.f, 0.f);
    float den = 0.f;
    for (int base = s; base < e; base += 32) {
        int cnt = min(32, e - base);
        float wv = 0.f; int sjv = 0;
        if (lane < cnt) {
            sjv = src[base + lane];
            float v = g_el2[sjv] + ern;
            v = v > 0.f ? v : 0.2f * v;
            wv = __expf(v);
        }
#pragma unroll 4
        for (int jj = 0; jj < cnt; ++jj) {
            float wt = __shfl_sync(0xffffffffu, wv, jj);
            int  sj  = __shfl_sync(0xffffffffu, sjv, jj);
            den += wt;
            __half2 f = *reinterpret_cast<const __half2*>(g_fs2h + (size_t)sj * 64 + lane * 2);
            fma_x2(acc, __half22float2(f), make_float2(wt, wt));
        }
    }

    float rden = (e > s) ? 1.f / den : 0.f;
    float* orow = out + (size_t)n * C2;
    int cc = lane * 2;
    if (cc < C2)     orow[cc]     = acc.x * rden + b2[cc];
    if (cc + 1 < C2) orow[cc + 1] = acc.y * rden + b2[cc + 1];
}

// ---------------- launch ----------------
extern "C" void kernel_launch(void* const* d_in, const int* in_sizes, int n_in,
                              void* d_out, int out_size)
{
    const float* x   = (const float*)d_in[0];
    const float* W1  = (const float*)d_in[1];
    const float* al1 = (const float*)d_in[2];
    const float* ar1 = (const float*)d_in[3];
    const float* b1  = (const float*)d_in[4];
    const float* W2  = (const float*)d_in[5];
    const float* al2 = (const float*)d_in[6];
    const float* ar2 = (const float*)d_in[7];
    const float* b2  = (const float*)d_in[8];
    const int*   src = (const int*)d_in[9];
    const int*   dst = (const int*)d_in[10];
    float* out = (float*)d_out;

    (void)in_sizes; (void)n_in; (void)out_size;

    cudaFuncSetAttribute(gemm1_mma_kernel,
                         cudaFuncAttributeMaxDynamicSharedMemorySize, GEMM_SMEM);
    cudaFuncSetAttribute(gemm2_mma_kernel,
                         cudaFuncAttributeMaxDynamicSharedMemorySize, GEMM2_SMEM);

    rowptr_kernel<<<(NN + 1 + 255) / 256, 256>>>(dst);
    wsplit_kernel<<<(65536 + 16384 + 255) / 256, 256>>>(W1, W2);

    // Layer 1
    gemm1_mma_kernel<<<NN_PAD / 128, 512, GEMM_SMEM>>>(x, al1, ar1);
    agg1_kernel<<<NN / 8, 256>>>(src, b1);

    // Layer 2
    gemm2_mma_kernel<<<NN_PAD / 128, 512, GEMM2_SMEM>>>(al2, ar2);
    agg2_kernel<<<NN / 8, 256>>>(src, b2, out);
}

// round 8
// speedup vs baseline: 4.0005x; 1.2572x over previous
#include <cuda_runtime.h>
#include <cuda_fp16.h>
#include <cstdint>

#define NN  50000
#define NE  800000
#define NN_PAD 50048              // 391 * 128
#define FIN 256
#define H1  4
#define D1  64
#define C2  47

// ---------------- scratch (device globals; no allocation allowed) ----------------
__device__ __align__(16) __half g_fs1[(size_t)NN * FIN];   // layer-1 features, fp16
__device__ __align__(16) __half g_h2 [(size_t)NN * FIN];   // relu(layer-1 out), fp16
__device__ __align__(16) __half g_fs2h[(size_t)NN * 64];   // layer-2 features, fp16 padded
__device__ __align__(16) float g_el1[NN * H1];
__device__ __align__(16) float g_er1[NN * H1];
__device__ __align__(16) float g_el2[NN];
__device__ __align__(16) float g_er2[NN];
__device__ __align__(16) int   g_rowptr[NN + 1];
// fp16 transposed weights: W1^T [256,256], W2^T padded [64,256]
__device__ __align__(16) __half g_w1h[256 * 256];
__device__ __align__(16) __half g_w2h[64 * 256];

// ================= warp-level MMA helpers (arch-agnostic PTX, sm_80+) =================
__device__ __forceinline__ uint32_t smem_to_u32(const void* p) {
    uint32_t a;
    asm("{ .reg .u64 t; cvta.to.shared.u64 t, %1; cvt.u32.u64 %0, t; }" : "=r"(a) : "l"(p));
    return a;
}
__device__ __forceinline__ void ldsm_x4(uint32_t addr, uint32_t r[4]) {
    asm volatile("ldmatrix.sync.aligned.m8n8.x4.shared.b16 {%0,%1,%2,%3}, [%4];"
                 : "=r"(r[0]), "=r"(r[1]), "=r"(r[2]), "=r"(r[3]) : "r"(addr));
}
__device__ __forceinline__ void ldsm_x2(uint32_t addr, uint32_t r[2]) {
    asm volatile("ldmatrix.sync.aligned.m8n8.x2.shared.b16 {%0,%1}, [%2];"
                 : "=r"(r[0]), "=r"(r[1]) : "r"(addr));
}
__device__ __forceinline__ void mma_f16(float c[4], const uint32_t a[4], const uint32_t b[2]) {
    asm volatile("mma.sync.aligned.m16n8k16.row.col.f32.f16.f16.f32 "
                 "{%0,%1,%2,%3}, {%4,%5,%6,%7}, {%8,%9}, {%0,%1,%2,%3};"
                 : "+f"(c[0]), "+f"(c[1]), "+f"(c[2]), "+f"(c[3])
                 : "r"(a[0]), "r"(a[1]), "r"(a[2]), "r"(a[3]), "r"(b[0]), "r"(b[1]));
}
__device__ __forceinline__ void fma_x2(float2& d, const float2& a, const float2& b)
{
    asm("fma.rn.f32x2 %0, %1, %2, %0;"
        : "+l"(reinterpret_cast<unsigned long long&>(d))
        : "l"(reinterpret_cast<const unsigned long long&>(a)),
          "l"(reinterpret_cast<const unsigned long long&>(b)));
}

// ================= prep: W transpose->fp16 + CSR rowptr, one kernel =================
__global__ void prep_kernel(const float* __restrict__ W1, const float* __restrict__ W2,
                            const int* __restrict__ dst)
{
    int idx = blockIdx.x * blockDim.x + threadIdx.x;
    if (idx < 65536) {
        int n = idx & 255, k = idx >> 8;
        g_w1h[(size_t)n * 256 + k] = __float2half_rn(W1[(size_t)k * 256 + n]);
    } else if (idx < 81920) {
        int j = idx - 65536;
        int n = j >> 8, k = j & 255;
        g_w2h[(size_t)n * 256 + k] = __float2half_rn((n < C2) ? W2[(size_t)k * C2 + n] : 0.f);
    } else if (idx < 81920 + NN + 1) {
        int n = idx - 81920;
        int lo = 0, hi = NE;
        while (lo < hi) {
            int mid = (lo + hi) >> 1;
            if (dst[mid] < n) lo = mid + 1; else hi = mid;
        }
        g_rowptr[n] = lo;
    }
}

// ================= fused GEMM + attention-logit kernels (single fp16 term) =============
#define LDT 264                       // padded row stride in 16-bit elems (528 B)
#define OFF_A 0
#define OFF_B (128 * LDT * 2)         // 67584
#define GEMM_SMEM (OFF_B + 64 * LDT * 2)   // 101376 B dynamic -> 2 CTAs/SM

// ---- load 128 fp32 rows of src (stride 256) -> fp16 smem tile ----
__device__ __forceinline__ void load_A_fp16(const float* __restrict__ src, int row0,
                                            __half* Aa, int tid)
{
#pragma unroll
    for (int i = 0; i < 16; ++i) {
        int idx = tid + i * 512;              // 0..8191 = 128 rows x 64 float4
        int r = idx >> 6, q = (idx & 63) * 4;
        int gr = row0 + r;
        float4 v = make_float4(0.f, 0.f, 0.f, 0.f);
        if (gr < NN) v = *reinterpret_cast<const float4*>(src + (size_t)gr * 256 + q);
        __half2 p0 = __floats2half2_rn(v.x, v.y);
        __half2 p1 = __floats2half2_rn(v.z, v.w);
        *reinterpret_cast<uint2*>(Aa + r * LDT + q) =
            make_uint2(*reinterpret_cast<uint32_t*>(&p0), *reinterpret_cast<uint32_t*>(&p1));
    }
}
// ---- copy 128 fp16 rows (stride 256) into padded smem tile ----
__device__ __forceinline__ void load_A_half(const __half* __restrict__ src, int row0,
                                            __half* Aa, int tid)
{
#pragma unroll
    for (int i = 0; i < 8; ++i) {
        int idx = tid + i * 512;              // 0..4095 = 128 rows x 32 uint4
        int r = idx >> 5, c8 = (idx & 31) * 8;
        int gr = row0 + r;
        uint4 v = make_uint4(0u, 0u, 0u, 0u);
        if (gr < NN) v = *reinterpret_cast<const uint4*>(src + (size_t)gr * 256 + c8);
        *reinterpret_cast<uint4*>(Aa + r * LDT + c8) = v;
    }
}
// ---- copy 64 fp16 rows (stride 256) into padded smem tile ----
__device__ __forceinline__ void load_B_half(const __half* __restrict__ src, int rowoff,
                                            __half* Bb, int tid)
{
#pragma unroll
    for (int i = 0; i < 4; ++i) {
        int idx = tid + i * 512;              // 0..2047 = 64 rows x 32 uint4
        int r = idx >> 5, c8 = (idx & 31) * 8;
        *reinterpret_cast<uint4*>(Bb + r * LDT + c8) =
            *reinterpret_cast<const uint4*>(src + (size_t)(rowoff + r) * 256 + c8);
    }
}

// ---- warp MMA over K=256, single fp16 term ----
__device__ __forceinline__ void mma_k256_f16(uint32_t sb, int m0, int n0, float c[4][4])
{
#pragma unroll
    for (int g = 0; g < 4; ++g)
#pragma unroll
        for (int q = 0; q < 4; ++q) c[g][q] = 0.f;
    const int lane = threadIdx.x & 31;
    uint32_t aA = sb + OFF_A + (uint32_t)((m0 + (lane & 15)) * LDT + ((lane >> 4) & 1) * 8) * 2;
    uint32_t aB = sb + OFF_B + (uint32_t)((n0 + (lane & 7)) * LDT + ((lane >> 3) & 1) * 8) * 2;
#pragma unroll
    for (int ks = 0; ks < 16; ++ks) {
        uint32_t fA[4];
        ldsm_x4(aA, fA);
#pragma unroll
        for (int g = 0; g < 4; ++g) {
            uint32_t b[2];
            ldsm_x2(aB + g * 8 * LDT * 2, b);
            mma_f16(c[g], fA, b);
        }
        aA += 32; aB += 32;
    }
}

// ================= GEMM1 (x @ W1) + el1/er1, 4 head-tiles per CTA; fs1 stored fp16 =========
__global__ void __launch_bounds__(512, 2) gemm1_mma_kernel(const float* __restrict__ x,
                                                           const float* __restrict__ al1,
                                                           const float* __restrict__ ar1)
{
    extern __shared__ __align__(16) char dsm[];
    __shared__ float als[256], ars[256];
    __shared__ float elp[2][128], erp[2][128];

    const uint32_t sb = smem_to_u32(dsm);
    const int tid  = threadIdx.x;
    const int lane = tid & 31;
    const int wid  = tid >> 5;
    const int wm = wid >> 1, wn = wid & 1;
    const int m0 = wm * 16, n0 = wn * 32;
    const int row0 = blockIdx.x * 128;

    __half* Aa = reinterpret_cast<__half*>(dsm + OFF_A);
    __half* Bb = reinterpret_cast<__half*>(dsm + OFF_B);

    load_A_fp16(x, row0, Aa, tid);
    if (tid < 256) { als[tid] = al1[tid]; ars[tid] = ar1[tid]; }

#pragma unroll 1
    for (int ct = 0; ct < 4; ++ct) {
        const int col0 = ct * 64;
        load_B_half(g_w1h, col0, Bb, tid);
        __syncthreads();

        float c[4][4];
        mma_k256_f16(sb, m0, n0, c);

        // ---- store C (fp16) + per-row attention partials for head ct ----
        const int r0 = row0 + m0 + (lane >> 2);
        const int cbl = n0 + 2 * (lane & 3);
        float pel0 = 0.f, per0 = 0.f, pel8 = 0.f, per8 = 0.f;
#pragma unroll
        for (int g = 0; g < 4; ++g) {
            float a0 = als[col0 + cbl + g * 8], a1 = als[col0 + cbl + g * 8 + 1];
            float b0 = ars[col0 + cbl + g * 8], b1 = ars[col0 + cbl + g * 8 + 1];
            pel0 += c[g][0] * a0 + c[g][1] * a1;
            per0 += c[g][0] * b0 + c[g][1] * b1;
            pel8 += c[g][2] * a0 + c[g][3] * a1;
            per8 += c[g][2] * b0 + c[g][3] * b1;
            if (r0 < NN)
                *reinterpret_cast<__half2*>(g_fs1 + (size_t)r0 * 256 + col0 + cbl + g * 8) =
                    __floats2half2_rn(c[g][0], c[g][1]);
            if (r0 + 8 < NN)
                *reinterpret_cast<__half2*>(g_fs1 + (size_t)(r0 + 8) * 256 + col0 + cbl + g * 8) =
                    __floats2half2_rn(c[g][2], c[g][3]);
        }
        pel0 += __shfl_xor_sync(0xffffffffu, pel0, 1); pel0 += __shfl_xor_sync(0xffffffffu, pel0, 2);
        per0 += __shfl_xor_sync(0xffffffffu, per0, 1); per0 += __shfl_xor_sync(0xffffffffu, per0, 2);
        pel8 += __shfl_xor_sync(0xffffffffu, pel8, 1); pel8 += __shfl_xor_sync(0xffffffffu, pel8, 2);
        per8 += __shfl_xor_sync(0xffffffffu, per8, 1); per8 += __shfl_xor_sync(0xffffffffu, per8, 2);
        if ((lane & 3) == 0) {
            int rr = m0 + (lane >> 2);
            elp[wn][rr] = pel0; elp[wn][rr + 8] = pel8;
            erp[wn][rr] = per0; erp[wn][rr + 8] = per8;
        }
        __syncthreads();
        if (tid < 128) {
            int row = row0 + tid;
            if (row < NN) {
                g_el1[row * 4 + ct] = elp[0][tid] + elp[1][tid];
                g_er1[row * 4 + ct] = erp[0][tid] + erp[1][tid];
            }
        }
    }
}

// ================= GEMM2 (h2 fp16 @ W2 fp16) + el2/er2; fs2 stored fp16 padded =======
__global__ void __launch_bounds__(512, 2) gemm2_mma_kernel(const float* __restrict__ al2,
                                                           const float* __restrict__ ar2)
{
    extern __shared__ __align__(16) char dsm[];
    __shared__ float als[64], ars[64];
    __shared__ float elp[2][128], erp[2][128];

    const uint32_t sb = smem_to_u32(dsm);
    const int tid  = threadIdx.x;
    const int lane = tid & 31;
    const int wid  = tid >> 5;
    const int wm = wid >> 1, wn = wid & 1;
    const int m0 = wm * 16, n0 = wn * 32;
    const int row0 = blockIdx.x * 128;

    __half* Aa = reinterpret_cast<__half*>(dsm + OFF_A);
    __half* Bb = reinterpret_cast<__half*>(dsm + OFF_B);

    load_A_half(g_h2, row0, Aa, tid);
    if (tid < 64) {
        als[tid] = (tid < C2) ? al2[tid] : 0.f;
        ars[tid] = (tid < C2) ? ar2[tid] : 0.f;
    }
    load_B_half(g_w2h, 0, Bb, tid);
    __syncthreads();

    float c[4][4];
    mma_k256_f16(sb, m0, n0, c);

    const int r0 = row0 + m0 + (lane >> 2);
    const int cbl = n0 + 2 * (lane & 3);
    float pel0 = 0.f, per0 = 0.f, pel8 = 0.f, per8 = 0.f;
#pragma unroll
    for (int g = 0; g < 4; ++g) {
        int cc = cbl + g * 8;
        float a0 = als[cc], a1 = als[cc + 1];
        float b0 = ars[cc], b1 = ars[cc + 1];
        pel0 += c[g][0] * a0 + c[g][1] * a1;
        per0 += c[g][0] * b0 + c[g][1] * b1;
        pel8 += c[g][2] * a0 + c[g][3] * a1;
        per8 += c[g][2] * b0 + c[g][3] * b1;
        if (r0 < NN)
            *reinterpret_cast<__half2*>(g_fs2h + (size_t)r0 * 64 + cc) =
                __floats2half2_rn(c[g][0], c[g][1]);
        if (r0 + 8 < NN)
            *reinterpret_cast<__half2*>(g_fs2h + (size_t)(r0 + 8) * 64 + cc) =
                __floats2half2_rn(c[g][2], c[g][3]);
    }
    pel0 += __shfl_xor_sync(0xffffffffu, pel0, 1); pel0 += __shfl_xor_sync(0xffffffffu, pel0, 2);
    per0 += __shfl_xor_sync(0xffffffffu, per0, 1); per0 += __shfl_xor_sync(0xffffffffu, per0, 2);
    pel8 += __shfl_xor_sync(0xffffffffu, pel8, 1); pel8 += __shfl_xor_sync(0xffffffffu, pel8, 2);
    per8 += __shfl_xor_sync(0xffffffffu, per8, 1); per8 += __shfl_xor_sync(0xffffffffu, per8, 2);
    if ((lane & 3) == 0) {
        int rr = m0 + (lane >> 2);
        elp[wn][rr] = pel0; elp[wn][rr + 8] = pel8;
        erp[wn][rr] = per0; erp[wn][rr + 8] = per8;
    }
    __syncthreads();
    if (tid < 128) {
        int row = row0 + tid;
        if (row < NN) {
            g_el2[row] = elp[0][tid] + elp[1][tid];
            g_er2[row] = erp[0][tid] + erp[1][tid];
        }
    }
}

// ---------------- layer-1 segment softmax + aggregation: WARP per dst node ----------------
__global__ void __launch_bounds__(256, 6) agg1_kernel(const int* __restrict__ src,
                                                      const float* __restrict__ b1)
{
    __shared__ float4 smw[8][32];
    __shared__ int    smsrc[8][32];

    const int w    = threadIdx.x >> 5;
    const int lane = threadIdx.x & 31;
    const int n    = blockIdx.x * 8 + w;
    const int s = g_rowptr[n];
    const int e = g_rowptr[n + 1];
    const float4 er = *reinterpret_cast<const float4*>(g_er1 + n * 4);

    const int h = lane >> 3;
    float2 acc2[4];
#pragma unroll
    for (int q = 0; q < 4; ++q) acc2[q] = make_float2(0.f, 0.f);
    float den = 0.f;

    for (int base = s; base < e; base += 32) {
        int cnt = min(32, e - base);
        if (lane < cnt) {
            int sj = src[base + lane];
            float4 el = *reinterpret_cast<const float4*>(g_el1 + sj * 4);
            float4 wv; float v;
            v = el.x + er.x; v = v > 0.f ? v : 0.2f * v; wv.x = __expf(v);
            v = el.y + er.y; v = v > 0.f ? v : 0.2f * v; wv.y = __expf(v);
            v = el.z + er.z; v = v > 0.f ? v : 0.2f * v; wv.z = __expf(v);
            v = el.w + er.w; v = v > 0.f ? v : 0.2f * v; wv.w = __expf(v);
            smw[w][lane]   = wv;
            smsrc[w][lane] = sj;
        }
        __syncwarp();
#pragma unroll 4
        for (int jj = 0; jj < cnt; ++jj) {
            float wt = reinterpret_cast<const float*>(&smw[w][jj])[h];
            int  sj  = smsrc[w][jj];
            den += wt;
            float2 w2 = make_float2(wt, wt);
            uint4 f = *reinterpret_cast<const uint4*>(g_fs1 + (size_t)sj * 256 + lane * 8);
            const __half2* hp = reinterpret_cast<const __half2*>(&f);
            fma_x2(acc2[0], __half22float2(hp[0]), w2);
            fma_x2(acc2[1], __half22float2(hp[1]), w2);
            fma_x2(acc2[2], __half22float2(hp[2]), w2);
            fma_x2(acc2[3], __half22float2(hp[3]), w2);
        }
        __syncwarp();
    }

    float rden = (e > s) ? 1.f / den : 0.f;
    float4 bb0 = *reinterpret_cast<const float4*>(b1 + lane * 8);
    float4 bb1 = *reinterpret_cast<const float4*>(b1 + lane * 8 + 4);
    __half2 o[4];
    o[0] = __floats2half2_rn(fmaxf(acc2[0].x * rden + bb0.x, 0.f), fmaxf(acc2[0].y * rden + bb0.y, 0.f));
    o[1] = __floats2half2_rn(fmaxf(acc2[1].x * rden + bb0.z, 0.f), fmaxf(acc2[1].y * rden + bb0.w, 0.f));
    o[2] = __floats2half2_rn(fmaxf(acc2[2].x * rden + bb1.x, 0.f), fmaxf(acc2[2].y * rden + bb1.y, 0.f));
    o[3] = __floats2half2_rn(fmaxf(acc2[3].x * rden + bb1.z, 0.f), fmaxf(acc2[3].y * rden + bb1.w, 0.f));
    *reinterpret_cast<uint4*>(g_h2 + (size_t)n * 256 + lane * 8) = *reinterpret_cast<uint4*>(o);
}

// ---------------- layer-2 segment softmax + aggregation: WARP per dst node, fp16 gather ----
__global__ void __launch_bounds__(256, 6) agg2_kernel(const int* __restrict__ src,
                                                      const float* __restrict__ b2,
                                                      float* __restrict__ out)
{
    const int w    = threadIdx.x >> 5;
    const int lane = threadIdx.x & 31;
    const int n    = blockIdx.x * 8 + w;
    const int s = g_rowptr[n];
    const int e = g_rowptr[n + 1];
    const float ern = g_er2[n];

    float2 acc = make_float2(0.f, 0.f);
    float den = 0.f;
    for (int base = s; base < e; base += 32) {
        int cnt = min(32, e - base);
        float wv = 0.f; int sjv = 0;
        if (lane < cnt) {
            sjv = src[base + lane];
            float v = g_el2[sjv] + ern;
            v = v > 0.f ? v : 0.2f * v;
            wv = __expf(v);
        }
#pragma unroll 4
        for (int jj = 0; jj < cnt; ++jj) {
            float wt = __shfl_sync(0xffffffffu, wv, jj);
            int  sj  = __shfl_sync(0xffffffffu, sjv, jj);
            den += wt;
            __half2 f = *reinterpret_cast<const __half2*>(g_fs2h + (size_t)sj * 64 + lane * 2);
            fma_x2(acc, __half22float2(f), make_float2(wt, wt));
        }
    }

    float rden = (e > s) ? 1.f / den : 0.f;
    float* orow = out + (size_t)n * C2;
    int cc = lane * 2;
    if (cc < C2)     orow[cc]     = acc.x * rden + b2[cc];
    if (cc + 1 < C2) orow[cc + 1] = acc.y * rden + b2[cc + 1];
}

// ---------------- launch ----------------
extern "C" void kernel_launch(void* const* d_in, const int* in_sizes, int n_in,
                              void* d_out, int out_size)
{
    const float* x   = (const float*)d_in[0];
    const float* W1  = (const float*)d_in[1];
    const float* al1 = (const float*)d_in[2];
    const float* ar1 = (const float*)d_in[3];
    const float* b1  = (const float*)d_in[4];
    const float* W2  = (const float*)d_in[5];
    const float* al2 = (const float*)d_in[6];
    const float* ar2 = (const float*)d_in[7];
    const float* b2  = (const float*)d_in[8];
    const int*   src = (const int*)d_in[9];
    const int*   dst = (const int*)d_in[10];
    float* out = (float*)d_out;

    (void)in_sizes; (void)n_in; (void)out_size;

    cudaFuncSetAttribute(gemm1_mma_kernel,
                         cudaFuncAttributeMaxDynamicSharedMemorySize, GEMM_SMEM);
    cudaFuncSetAttribute(gemm2_mma_kernel,
                         cudaFuncAttributeMaxDynamicSharedMemorySize, GEMM_SMEM);

    prep_kernel<<<(81920 + NN + 1 + 255) / 256, 256>>>(W1, W2, dst);

    // Layer 1
    gemm1_mma_kernel<<<NN_PAD / 128, 512, GEMM_SMEM>>>(x, al1, ar1);
    agg1_kernel<<<NN / 8, 256>>>(src, b1);

    // Layer 2
    gemm2_mma_kernel<<<NN_PAD / 128, 512, GEMM_SMEM>>>(al2, ar2);
    agg2_kernel<<<NN / 8, 256>>>(src, b2, out);
}